// round 14
// baseline (speedup 1.0000x reference)
#include <cuda_runtime.h>
#include <cuda_bf16.h>
#include <math.h>
#include <stdint.h>

#define HID    1024
#define FFDIM  4096
#define NHEAD  16
#define HD     64
#define BATCH  4
#define SEQ    1024
#define NTOK   (BATCH*SEQ)
#define MAXPOS 1024

// ---------------- scratch ----------------
__device__ __nv_bfloat16 g_qh[NTOK * HID];
__device__ __nv_bfloat16 g_kh[NTOK * HID];
__device__ __nv_bfloat16 g_vh[NTOK * HID];
__device__ __nv_bfloat16 g_disth[(2 * MAXPOS - 1) * HD];
__device__ float g_ctx[NTOK * HID];
__device__ float g_tmp[NTOK * HID];
__device__ float g_attnout[NTOK * HID];
__device__ float g_attnout_tf[NTOK * HID];
__device__ float g_inter[NTOK * FFDIM];
__device__ float g_hs_tf[NTOK * HID];
// transposed (n-major) tf32-rounded weights
__device__ float g_wqt[HID * HID];
__device__ float g_wkt[HID * HID];
__device__ float g_wvt[HID * HID];
__device__ float g_wot[HID * HID];
__device__ float g_wit[FFDIM * HID];
__device__ float g_wo2t[HID * FFDIM];

// ---------------- helpers ----------------
__device__ __forceinline__ uint32_t f2tf(float f) {
    uint32_t u;
    asm("cvt.rna.tf32.f32 %0, %1;" : "=r"(u) : "f"(f));
    return u;
}

__device__ __forceinline__ uint32_t pack_bf2(float x, float y) {
    __nv_bfloat162 h = __floats2bfloat162_rn(x, y);
    return *(uint32_t*)&h;
}

__device__ __forceinline__ uint32_t smem_u32(const void* p) {
    return (uint32_t)__cvta_generic_to_shared(p);
}

__device__ __forceinline__ void mma_tf32(float c[4], const uint32_t a[4],
                                         const uint32_t b[2]) {
    asm volatile(
        "mma.sync.aligned.m16n8k8.row.col.f32.tf32.tf32.f32 "
        "{%0,%1,%2,%3}, {%4,%5,%6,%7}, {%8,%9}, {%0,%1,%2,%3};"
        : "+f"(c[0]), "+f"(c[1]), "+f"(c[2]), "+f"(c[3])
        : "r"(a[0]), "r"(a[1]), "r"(a[2]), "r"(a[3]), "r"(b[0]), "r"(b[1]));
}

__device__ __forceinline__ void mma_bf16(float c[4], const uint32_t a[4],
                                         const uint32_t b[2]) {
    asm volatile(
        "mma.sync.aligned.m16n8k16.row.col.f32.bf16.bf16.f32 "
        "{%0,%1,%2,%3}, {%4,%5,%6,%7}, {%8,%9}, {%0,%1,%2,%3};"
        : "+f"(c[0]), "+f"(c[1]), "+f"(c[2]), "+f"(c[3])
        : "r"(a[0]), "r"(a[1]), "r"(a[2]), "r"(a[3]), "r"(b[0]), "r"(b[1]));
}

__device__ __forceinline__ void ldsm_x4(uint32_t* r, uint32_t a) {
    asm volatile("ldmatrix.sync.aligned.m8n8.x4.shared.b16 {%0,%1,%2,%3}, [%4];"
        : "=r"(r[0]), "=r"(r[1]), "=r"(r[2]), "=r"(r[3]) : "r"(a));
}
__device__ __forceinline__ void ldsm_x2(uint32_t* r, uint32_t a) {
    asm volatile("ldmatrix.sync.aligned.m8n8.x2.shared.b16 {%0,%1}, [%2];"
        : "=r"(r[0]), "=r"(r[1]) : "r"(a));
}
__device__ __forceinline__ void ldsm_x2t(uint32_t* r, uint32_t a) {
    asm volatile("ldmatrix.sync.aligned.m8n8.x2.trans.shared.b16 {%0,%1}, [%2];"
        : "=r"(r[0]), "=r"(r[1]) : "r"(a));
}

__device__ __forceinline__ void cp16(void* smem, const void* gmem) {
    uint32_t s = (uint32_t)__cvta_generic_to_shared(smem);
    asm volatile("cp.async.cg.shared.global [%0], [%1], 16;" :: "r"(s), "l"(gmem));
}
#define CP_COMMIT() asm volatile("cp.async.commit_group;")
#define CP_WAIT0()  asm volatile("cp.async.wait_group 0;")

// ---------------- weight transpose + tf32 round: in[R][C] -> out[C][R] ------
__global__ void __launch_bounds__(256) transpose_tf(
    const float* __restrict__ in, float* __restrict__ out, int R, int C)
{
    __shared__ float t[32][33];
    const int c0 = blockIdx.x * 32;
    const int r0 = blockIdx.y * 32;
    const int tx = threadIdx.x;       // 0..31
    const int ty = threadIdx.y;       // 0..7
#pragma unroll
    for (int i = ty; i < 32; i += 8)
        t[i][tx] = in[(size_t)(r0 + i) * C + c0 + tx];
    __syncthreads();
#pragma unroll
    for (int i = ty; i < 32; i += 8)
        out[(size_t)(c0 + i) * R + r0 + tx] = __uint_as_float(f2tf(t[tx][i]));
}

// ---------------- hs tf32-round + dist bf16 convert --------------------------
#define CVT2_SEG1 1048576           // hs float4 count
#define CVT2_TOTAL (CVT2_SEG1 + 32752)

__global__ void __launch_bounds__(256) cvt_hs_dist(
    const float* __restrict__ hs, const float* __restrict__ dist,
    float* __restrict__ hs_tf, __nv_bfloat16* __restrict__ disth)
{
    int idx = blockIdx.x * blockDim.x + threadIdx.x;
    if (idx < CVT2_SEG1) {
        float4 v = ((const float4*)hs)[idx];
        v.x = __uint_as_float(f2tf(v.x));
        v.y = __uint_as_float(f2tf(v.y));
        v.z = __uint_as_float(f2tf(v.z));
        v.w = __uint_as_float(f2tf(v.w));
        ((float4*)hs_tf)[idx] = v;
    } else if (idx < CVT2_TOTAL) {
        const int rel = idx - CVT2_SEG1;
        float4 v = ((const float4*)dist)[rel];
        ((uint2*)disth)[rel] = make_uint2(pack_bf2(v.x, v.y), pack_bf2(v.z, v.w));
    }
}

// ---------------- 2-stage tf32 GEMM, ldmatrix fragments, Bt n-major ----------
// A [M][K] row-major; Bt [N][K] row-major (pre-transposed weights).
#define GA(s,r,c)  ((( (s)*128 + (r) )*36) + (c))
#define GEMM_SMEM_BYTES (2 * (2*128*36) * 4)
#define STG_STRIDE (128 * 36 * 4)   // stage stride in bytes

template <int GELU, int ROUND, int BFOUT>
__device__ __forceinline__ void gemm_body(
    const float* __restrict__ A, const float* __restrict__ Bt,
    const float* __restrict__ bias, void* __restrict__ Cout,
    int M, int N, int K, float* sm)
{
    float* As = sm;
    float* Bs = sm + 2 * 128 * 36;

    const int tid = threadIdx.x;
    const int w   = tid >> 5;
    const int l   = tid & 31;
    const int wr  = w >> 2;
    const int wc  = w & 3;
    const int m0  = blockIdx.y * 128;
    const int n0  = blockIdx.x * 128;
    const int g   = l >> 2;
    const int t4  = l & 3;

    // staging: both tiles are [128][32] float
    const int ar = tid >> 3;            // 0..31 (+32i)
    const int ac = (tid & 7) << 2;      // 0..28

    // ldmatrix lane base addresses (stage 0)
    const uint32_t aA0 = smem_u32(&As[GA(0, wr * 64 + (l & 15), ((l >> 4) << 2))]);
    const uint32_t aB0 = smem_u32(&Bs[GA(0, wc * 32 + (l & 7), (((l >> 3) & 1) << 2))]);

    float c[4][4][4];
#pragma unroll
    for (int mi = 0; mi < 4; mi++)
#pragma unroll
        for (int ni = 0; ni < 4; ni++)
#pragma unroll
            for (int r = 0; r < 4; r++) c[mi][ni][r] = 0.f;

#pragma unroll
    for (int i = 0; i < 4; i++)
        cp16(&As[GA(0, ar + 32 * i, ac)], &A[(size_t)(m0 + ar + 32 * i) * K + ac]);
#pragma unroll
    for (int i = 0; i < 4; i++)
        cp16(&Bs[GA(0, ar + 32 * i, ac)], &Bt[(size_t)(n0 + ar + 32 * i) * K + ac]);
    CP_COMMIT();

    for (int k0 = 0; k0 < K; k0 += 32) {
        const int s = (k0 >> 5) & 1;
        CP_WAIT0();
        __syncthreads();
        if (k0 + 32 < K) {
            const int ns = s ^ 1;
            const int nk = k0 + 32;
#pragma unroll
            for (int i = 0; i < 4; i++)
                cp16(&As[GA(ns, ar + 32 * i, ac)],
                     &A[(size_t)(m0 + ar + 32 * i) * K + nk + ac]);
#pragma unroll
            for (int i = 0; i < 4; i++)
                cp16(&Bs[GA(ns, ar + 32 * i, ac)],
                     &Bt[(size_t)(n0 + ar + 32 * i) * K + nk + ac]);
            CP_COMMIT();
        }

        const uint32_t aA = aA0 + s * STG_STRIDE;
        const uint32_t aB = aB0 + s * STG_STRIDE;
#pragma unroll
        for (int kk = 0; kk < 4; kk++) {
            uint32_t a[4][4], b[4][2];
#pragma unroll
            for (int mi = 0; mi < 4; mi++)
                ldsm_x4(a[mi], aA + mi * (16 * 36 * 4) + kk * 32);
#pragma unroll
            for (int ni = 0; ni < 4; ni++)
                ldsm_x2(b[ni], aB + ni * (8 * 36 * 4) + kk * 32);
#pragma unroll
            for (int mi = 0; mi < 4; mi++)
#pragma unroll
                for (int ni = 0; ni < 4; ni++)
                    mma_tf32(c[mi][ni], a[mi], b[ni]);
        }
    }

#pragma unroll
    for (int mi = 0; mi < 4; mi++) {
#pragma unroll
        for (int ni = 0; ni < 4; ni++) {
            const int row = m0 + wr * 64 + mi * 16 + g;
            const int col = n0 + wc * 32 + ni * 8 + t4 * 2;
            const float b0 = bias[col], b1 = bias[col + 1];
            float v0 = c[mi][ni][0] + b0;
            float v1 = c[mi][ni][1] + b1;
            float v2 = c[mi][ni][2] + b0;
            float v3 = c[mi][ni][3] + b1;
            if (GELU) {
                v0 = 0.5f * v0 * (1.0f + erff(v0 * 0.70710678118654752f));
                v1 = 0.5f * v1 * (1.0f + erff(v1 * 0.70710678118654752f));
                v2 = 0.5f * v2 * (1.0f + erff(v2 * 0.70710678118654752f));
                v3 = 0.5f * v3 * (1.0f + erff(v3 * 0.70710678118654752f));
            }
            if (BFOUT) {
                __nv_bfloat16* C = (__nv_bfloat16*)Cout;
                *(uint32_t*)&C[(size_t)row * N + col]       = pack_bf2(v0, v1);
                *(uint32_t*)&C[(size_t)(row + 8) * N + col] = pack_bf2(v2, v3);
            } else {
                float* C = (float*)Cout;
                if (ROUND) {
                    v0 = __uint_as_float(f2tf(v0));
                    v1 = __uint_as_float(f2tf(v1));
                    v2 = __uint_as_float(f2tf(v2));
                    v3 = __uint_as_float(f2tf(v3));
                }
                *(float2*)&C[(size_t)row * N + col]       = make_float2(v0, v1);
                *(float2*)&C[(size_t)(row + 8) * N + col] = make_float2(v2, v3);
            }
        }
    }
}

template <int GELU, int ROUND>
__global__ void __launch_bounds__(256) gemm_db(
    const float* __restrict__ A, const float* __restrict__ Bt,
    const float* __restrict__ bias, float* __restrict__ C,
    int M, int N, int K)
{
    extern __shared__ float sm[];
    gemm_body<GELU, ROUND, 0>(A, Bt, bias, C, M, N, K, sm);
}

__global__ void __launch_bounds__(256) qkv_db(
    const float* __restrict__ A,
    const float* __restrict__ W0, const float* __restrict__ W1, const float* __restrict__ W2,
    const float* __restrict__ b0, const float* __restrict__ b1, const float* __restrict__ b2,
    __nv_bfloat16* __restrict__ o0, __nv_bfloat16* __restrict__ o1,
    __nv_bfloat16* __restrict__ o2)
{
    extern __shared__ float sm[];
    const int z = blockIdx.z;
    const float* W = (z == 0) ? W0 : (z == 1) ? W1 : W2;
    const float* bb = (z == 0) ? b0 : (z == 1) ? b1 : b2;
    __nv_bfloat16* O = (z == 0) ? o0 : (z == 1) ? o1 : o2;
    gemm_body<0, 0, 1>(A, W, bb, O, NTOK, HID, HID, sm);
}

// ---------------- LayerNorm(x + res) * g + b ----------------
__global__ void __launch_bounds__(256) ln_residual(
    const float* __restrict__ x, const float* __restrict__ res,
    const float* __restrict__ g, const float* __restrict__ b,
    float* __restrict__ out, float* __restrict__ out_tf)
{
    __shared__ float red[8];
    const int row = blockIdx.x;
    const int tid = threadIdx.x;
    const size_t base = (size_t)row * HID + tid * 4;

    float4 xv = *(const float4*)&x[base];
    float4 rv = *(const float4*)&res[base];
    float v0 = xv.x + rv.x, v1 = xv.y + rv.y, v2 = xv.z + rv.z, v3 = xv.w + rv.w;

    float s = v0 + v1 + v2 + v3;
#pragma unroll
    for (int o = 16; o; o >>= 1) s += __shfl_xor_sync(0xffffffffu, s, o);
    if ((tid & 31) == 0) red[tid >> 5] = s;
    __syncthreads();
    if (tid < 8) {
        s = red[tid];
#pragma unroll
        for (int o = 4; o; o >>= 1) s += __shfl_xor_sync(0xffu, s, o, 8);
        if (tid == 0) red[0] = s;
    }
    __syncthreads();
    const float mean = red[0] * (1.0f / HID);
    __syncthreads();

    float d0 = v0 - mean, d1 = v1 - mean, d2 = v2 - mean, d3 = v3 - mean;
    float vs = d0 * d0 + d1 * d1 + d2 * d2 + d3 * d3;
#pragma unroll
    for (int o = 16; o; o >>= 1) vs += __shfl_xor_sync(0xffffffffu, vs, o);
    if ((tid & 31) == 0) red[tid >> 5] = vs;
    __syncthreads();
    if (tid < 8) {
        vs = red[tid];
#pragma unroll
        for (int o = 4; o; o >>= 1) vs += __shfl_xor_sync(0xffu, vs, o, 8);
        if (tid == 0) red[0] = vs;
    }
    __syncthreads();
    const float inv = rsqrtf(red[0] * (1.0f / HID) + 1e-12f);

    float4 gv = *(const float4*)&g[tid * 4];
    float4 bv = *(const float4*)&b[tid * 4];
    float4 ov;
    ov.x = d0 * inv * gv.x + bv.x;
    ov.y = d1 * inv * gv.y + bv.y;
    ov.z = d2 * inv * gv.z + bv.z;
    ov.w = d3 * inv * gv.w + bv.w;
    *(float4*)&out[base] = ov;
    if (out_tf) {
        float4 tv;
        tv.x = __uint_as_float(f2tf(ov.x));
        tv.y = __uint_as_float(f2tf(ov.y));
        tv.z = __uint_as_float(f2tf(ov.z));
        tv.w = __uint_as_float(f2tf(ov.w));
        *(float4*)&out_tf[base] = tv;
    }
}

// ---------------- bf16 TC attention (unchanged from R10) ---------------------
#define HST 72
#define BSTH 132
#define ATTN_SMEM_BYTES 108544

__global__ void __launch_bounds__(256, 2) attn_tc(
    const __nv_bfloat16* __restrict__ Q, const __nv_bfloat16* __restrict__ K,
    const __nv_bfloat16* __restrict__ V, const __nv_bfloat16* __restrict__ disth,
    const float* __restrict__ mask, const float* __restrict__ hm,
    float* __restrict__ ctx)
{
    extern __shared__ char smb[];
    __nv_bfloat16* Qh  = (__nv_bfloat16*)smb;
    __nv_bfloat16* Kh  = Qh + 64 * HST;
    __nv_bfloat16* Er  = Kh + 2 * 64 * HST;
    __nv_bfloat16* Vh  = Er + 128 * HST;
    __nv_bfloat16* B1h = Vh + 2 * 64 * HST;
    __nv_bfloat16* B2h = B1h + 64 * BSTH;
    __nv_bfloat16* Ph  = B2h + 64 * BSTH;
    float*         Rmax = (float*)(Ph + 64 * HST);
    float*         Rsum = Rmax + 128;

    const int tid = threadIdx.x;
    const int w   = tid >> 5;
    const int wm  = w & 3;
    const int wn  = w >> 2;
    const int l   = tid & 31;
    const int g   = l >> 2;
    const int t4  = l & 3;
    const int bh  = blockIdx.y;
    const int b   = bh >> 4;
    const int h   = bh & 15;
    const int l0  = blockIdx.x * 64;

    const int li0 = 16 * wm + g;
    const int li1 = li0 + 8;

    const int arow = 16 * wm + (l & 15);
    const int acol = (l >> 4) << 3;
    const uint32_t aQ = smem_u32(&Qh[arow * HST + acol]);
    const uint32_t aP = smem_u32(&Ph[arow * HST + acol]);
    const uint32_t aKb[2] = { smem_u32(&Kh[arow * HST + acol]),
                              smem_u32(&Kh[64 * HST + arow * HST + acol]) };
    const int brow = l & 7;
    const int bcol = ((l >> 3) & 1) << 3;
    const uint32_t bKb[2] = { smem_u32(&Kh[brow * HST + bcol]),
                              smem_u32(&Kh[64 * HST + brow * HST + bcol]) };
    const uint32_t bEbase = smem_u32(Er) + bcol * 2;
    const uint32_t bVb[2] = { smem_u32(&Vh[(l & 15) * HST]),
                              smem_u32(&Vh[64 * HST + (l & 15) * HST]) };

    const __nv_bfloat16* Qg = Q + (size_t)(b * SEQ + l0) * HID + h * HD;
    const __nv_bfloat16* Kg = K + (size_t)(b * SEQ) * HID + h * HD;
    const __nv_bfloat16* Vg = V + (size_t)(b * SEQ) * HID + h * HD;
    const float* mg = mask + b * SEQ;

    for (int idx = tid; idx < 512; idx += 256) {
        int r = idx >> 3, c8 = (idx & 7) << 3;
        cp16(&Qh[r * HST + c8], &Qg[(size_t)r * HID + c8]);
    }
    {
        const int dbase0 = l0 + 960;
        for (int idx = tid; idx < 1024; idx += 256) {
            int r = idx >> 3, c8 = (idx & 7) << 3;
            int row = dbase0 + r;
            int rowc = row > 2046 ? 2046 : row;
            cp16(&Er[(row & 127) * HST + c8], &disth[(size_t)rowc * HD + c8]);
        }
        for (int idx = tid; idx < 512; idx += 256) {
            int r = idx >> 3, c8 = (idx & 7) << 3;
            cp16(&Kh[r * HST + c8], &Kg[(size_t)r * HID + c8]);
            cp16(&Vh[r * HST + c8], &Vg[(size_t)r * HID + c8]);
        }
    }
    CP_COMMIT();
    CP_WAIT0();
    __syncthreads();

    uint32_t aq[4][4];
#pragma unroll
    for (int kk = 0; kk < 4; kk++) ldsm_x4(aq[kk], aQ + kk * 32);

    float O[4][4];
#pragma unroll
    for (int ni = 0; ni < 4; ni++)
#pragma unroll
        for (int r = 0; r < 4; r++) O[ni][r] = 0.f;
    float mrow[2] = {-1e30f, -1e30f};
    float lrow[2] = {0.f, 0.f};

    const int j0 = 48 - 16 * wm + wn * 40;

    for (int rt = 0; rt < 16; rt++) {
        const int r0 = rt * 64;
        const int dbase = l0 - r0 + 960;
        const int buf = rt & 1;
        if (rt) {
            CP_WAIT0();
            __syncthreads();
        }

        if (rt < 15) {
            const int nbuf = buf ^ 1;
            const int nr0 = r0 + 64;
            for (int idx = tid; idx < 512; idx += 256) {
                int r = idx >> 3, c8 = (idx & 7) << 3;
                cp16(&Kh[nbuf * 64 * HST + r * HST + c8],
                     &Kg[(size_t)(nr0 + r) * HID + c8]);
                cp16(&Vh[nbuf * 64 * HST + r * HST + c8],
                     &Vg[(size_t)(nr0 + r) * HID + c8]);
            }
            CP_COMMIT();
        }

        uint32_t ak[4][4];
#pragma unroll
        for (int kk = 0; kk < 4; kk++) ldsm_x4(ak[kk], aKb[buf] + kk * 32);

        {
            float c[5][4];
#pragma unroll
            for (int ni = 0; ni < 5; ni++)
#pragma unroll
                for (int r = 0; r < 4; r++) c[ni][r] = 0.f;
#pragma unroll
            for (int kk = 0; kk < 4; kk++) {
#pragma unroll
                for (int ni = 0; ni < 5; ni++) {
                    const int j = j0 + ni * 8;
                    const int slot = (dbase + j + brow) & 127;
                    uint32_t bf[2];
                    ldsm_x2(bf, bEbase + slot * (HST * 2) + kk * 32);
                    mma_bf16(c[ni], ak[kk], bf);
                }
            }
#pragma unroll
            for (int ni = 0; ni < 5; ni++) {
                const int col = j0 + ni * 8 + 2 * t4;
                *(uint32_t*)&B2h[li0 * BSTH + col] = pack_bf2(c[ni][0], c[ni][1]);
                *(uint32_t*)&B2h[li1 * BSTH + col] = pack_bf2(c[ni][2], c[ni][3]);
            }
        }

        const int nblk = (rt == 0) ? 2 : 1;
        for (int blk = 0; blk < nblk; blk++) {
            const int base = (dbase + 64 * blk) & 127;
            float c[4][4];
#pragma unroll
            for (int ni = 0; ni < 4; ni++)
#pragma unroll
                for (int r = 0; r < 4; r++) c[ni][r] = 0.f;
#pragma unroll
            for (int kk = 0; kk < 4; kk++) {
#pragma unroll
                for (int ni = 0; ni < 4; ni++) {
                    const int slot = base + wn * 32 + ni * 8 + brow;
                    uint32_t bf[2];
                    ldsm_x2(bf, bEbase + slot * (HST * 2) + kk * 32);
                    mma_bf16(c[ni], aq[kk], bf);
                }
            }
#pragma unroll
            for (int ni = 0; ni < 4; ni++) {
                const int col = base + wn * 32 + ni * 8 + 2 * t4;
                *(uint32_t*)&B1h[li0 * BSTH + col] = pack_bf2(c[ni][0], c[ni][1]);
                *(uint32_t*)&B1h[li1 * BSTH + col] = pack_bf2(c[ni][2], c[ni][3]);
            }
        }

        float cS[4][4];
#pragma unroll
        for (int ni = 0; ni < 4; ni++)
#pragma unroll
            for (int r = 0; r < 4; r++) cS[ni][r] = 0.f;
#pragma unroll
        for (int kk = 0; kk < 4; kk++) {
#pragma unroll
            for (int ni = 0; ni < 4; ni++) {
                const int ncol = wn * 32 + ni * 8;
                uint32_t bf[2];
                ldsm_x2(bf, bKb[buf] + (ncol * HST) * 2 + kk * 32);
                mma_bf16(cS[ni], aq[kk], bf);
            }
        }
        __syncthreads();

        if (rt < 15) {
            const int ndbase = dbase - 64;
            for (int idx = tid; idx < 512; idx += 256) {
                int r = idx >> 3, c8 = (idx & 7) << 3;
                int row = ndbase + r;
                cp16(&Er[(row & 127) * HST + c8], &disth[(size_t)row * HD + c8]);
            }
            CP_COMMIT();
        }

        const int dofs = dbase + 63;
        float vmax0 = -1e30f, vmax1 = -1e30f;
#pragma unroll
        for (int ni = 0; ni < 4; ni++) {
#pragma unroll
            for (int e = 0; e < 2; e++) {
                const int rj = wn * 32 + ni * 8 + 2 * t4 + e;
                const float mv = mg[r0 + rj];
                const int s0 = (dofs + li0 - rj) & 127;
                const int s1 = (dofs + li1 - rj) & 127;
                const int ib0 = li0 - rj + 63;
                const int ib1 = li1 - rj + 63;
                float b1a = __bfloat162float(B1h[li0 * BSTH + s0]);
                float b1b = __bfloat162float(B1h[li1 * BSTH + s1]);
                float b2a = __bfloat162float(B2h[rj * BSTH + ib0]);
                float b2b = __bfloat162float(B2h[rj * BSTH + ib1]);
                float v0 = (cS[ni][e]     + b1a + b2a) * 0.125f + mv;
                float v1 = (cS[ni][2 + e] + b1b + b2b) * 0.125f + mv;
                cS[ni][e]     = v0;
                cS[ni][2 + e] = v1;
                vmax0 = fmaxf(vmax0, v0);
                vmax1 = fmaxf(vmax1, v1);
            }
        }
        vmax0 = fmaxf(vmax0, __shfl_xor_sync(0xffffffffu, vmax0, 1));
        vmax0 = fmaxf(vmax0, __shfl_xor_sync(0xffffffffu, vmax0, 2));
        vmax1 = fmaxf(vmax1, __shfl_xor_sync(0xffffffffu, vmax1, 1));
        vmax1 = fmaxf(vmax1, __shfl_xor_sync(0xffffffffu, vmax1, 2));
        if (t4 == 0) {
            Rmax[wn * 64 + li0] = vmax0;
            Rmax[wn * 64 + li1] = vmax1;
        }
        __syncthreads();
        vmax0 = fmaxf(vmax0, Rmax[(wn ^ 1) * 64 + li0]);
        vmax1 = fmaxf(vmax1, Rmax[(wn ^ 1) * 64 + li1]);

        const float nm0 = fmaxf(mrow[0], vmax0);
        const float nm1 = fmaxf(mrow[1], vmax1);
        const float corr0 = __expf(mrow[0] - nm0);
        const float corr1 = __expf(mrow[1] - nm1);

        float ts0 = 0.f, ts1 = 0.f;
#pragma unroll
        for (int ni = 0; ni < 4; ni++) {
            const int cj = wn * 32 + ni * 8 + 2 * t4;
            float p00 = __expf(cS[ni][0] - nm0);
            float p01 = __expf(cS[ni][1] - nm0);
            float p10 = __expf(cS[ni][2] - nm1);
            float p11 = __expf(cS[ni][3] - nm1);
            *(uint32_t*)&Ph[li0 * HST + cj] = pack_bf2(p00, p01);
            *(uint32_t*)&Ph[li1 * HST + cj] = pack_bf2(p10, p11);
            ts0 += p00 + p01;
            ts1 += p10 + p11;
        }
        ts0 += __shfl_xor_sync(0xffffffffu, ts0, 1);
        ts0 += __shfl_xor_sync(0xffffffffu, ts0, 2);
        ts1 += __shfl_xor_sync(0xffffffffu, ts1, 1);
        ts1 += __shfl_xor_sync(0xffffffffu, ts1, 2);
        if (t4 == 0) {
            Rsum[wn * 64 + li0] = ts0;
            Rsum[wn * 64 + li1] = ts1;
        }
        __syncthreads();
        ts0 += Rsum[(wn ^ 1) * 64 + li0];
        ts1 += Rsum[(wn ^ 1) * 64 + li1];

        lrow[0] = lrow[0] * corr0 + ts0;
        lrow[1] = lrow[1] * corr1 + ts1;
        mrow[0] = nm0;
        mrow[1] = nm1;
#pragma unroll
        for (int ni = 0; ni < 4; ni++) {
            O[ni][0] *= corr0;
            O[ni][1] *= corr0;
            O[ni][2] *= corr1;
            O[ni][3] *= corr1;
        }

#pragma unroll
        for (int kk = 0; kk < 4; kk++) {
            const int kb = kk * 16;
            uint32_t ap[4];
            ldsm_x4(ap, aP + kk * 32);
#pragma unroll
            for (int ni = 0; ni < 4; ni++) {
                const int nbase = wn * 32 + ni * 8;
                uint32_t bf[2];
                ldsm_x2t(bf, bVb[buf] + (kb * HST + nbase) * 2);
                mma_bf16(O[ni], ap, bf);
            }
        }
    }

    const float hscale = hm[h];
    const float inv0 = hscale / lrow[0];
    const float inv1 = hscale / lrow[1];
#pragma unroll
    for (int ni = 0; ni < 4; ni++) {
        const int col = h * HD + wn * 32 + ni * 8 + 2 * t4;
        const size_t row0g = (size_t)(b * SEQ + l0 + li0) * HID + col;
        const size_t row1g = (size_t)(b * SEQ + l0 + li1) * HID + col;
        float c00 = __uint_as_float(f2tf(O[ni][0] * inv0));
        float c01 = __uint_as_float(f2tf(O[ni][1] * inv0));
        float c10 = __uint_as_float(f2tf(O[ni][2] * inv1));
        float c11 = __uint_as_float(f2tf(O[ni][3] * inv1));
        *(float2*)&ctx[row0g] = make_float2(c00, c01);
        *(float2*)&ctx[row1g] = make_float2(c10, c11);
    }
}

// ---------------- launch ----------------
extern "C" void kernel_launch(void* const* d_in, const int* in_sizes, int n_in,
                              void* d_out, int out_size)
{
    const float* hs   = (const float*)d_in[0];
    const float* mask = (const float*)d_in[1];
    const float* hm   = (const float*)d_in[2];
    const float* Wq   = (const float*)d_in[3];
    const float* bq   = (const float*)d_in[4];
    const float* Wk   = (const float*)d_in[5];
    const float* bk   = (const float*)d_in[6];
    const float* Wv   = (const float*)d_in[7];
    const float* bv   = (const float*)d_in[8];
    const float* dist = (const float*)d_in[9];
    const float* Wo   = (const float*)d_in[10];
    const float* bo   = (const float*)d_in[11];
    const float* ln1g = (const float*)d_in[12];
    const float* ln1b = (const float*)d_in[13];
    const float* Wi   = (const float*)d_in[14];
    const float* bi   = (const float*)d_in[15];
    const float* Wo2  = (const float*)d_in[16];
    const float* bo2  = (const float*)d_in[17];
    const float* ln2g = (const float*)d_in[18];
    const float* ln2b = (const float*)d_in[19];
    float* out = (float*)d_out;

    __nv_bfloat16 *qh, *kh, *vh, *disth;
    float *ctx, *tmp, *attnout, *attnout_tf, *inter;
    float *hs_tf, *wqt, *wkt, *wvt, *wot, *wit, *wo2t;
    cudaGetSymbolAddress((void**)&qh,         g_qh);
    cudaGetSymbolAddress((void**)&kh,         g_kh);
    cudaGetSymbolAddress((void**)&vh,         g_vh);
    cudaGetSymbolAddress((void**)&disth,      g_disth);
    cudaGetSymbolAddress((void**)&ctx,        g_ctx);
    cudaGetSymbolAddress((void**)&tmp,        g_tmp);
    cudaGetSymbolAddress((void**)&attnout,    g_attnout);
    cudaGetSymbolAddress((void**)&attnout_tf, g_attnout_tf);
    cudaGetSymbolAddress((void**)&inter,      g_inter);
    cudaGetSymbolAddress((void**)&hs_tf,      g_hs_tf);
    cudaGetSymbolAddress((void**)&wqt,        g_wqt);
    cudaGetSymbolAddress((void**)&wkt,        g_wkt);
    cudaGetSymbolAddress((void**)&wvt,        g_wvt);
    cudaGetSymbolAddress((void**)&wot,        g_wot);
    cudaGetSymbolAddress((void**)&wit,        g_wit);
    cudaGetSymbolAddress((void**)&wo2t,       g_wo2t);

    cudaFuncSetAttribute(attn_tc, cudaFuncAttributeMaxDynamicSharedMemorySize,
                         ATTN_SMEM_BYTES);
    cudaFuncSetAttribute((const void*)gemm_db<0,0>,
                         cudaFuncAttributeMaxDynamicSharedMemorySize, GEMM_SMEM_BYTES);
    cudaFuncSetAttribute((const void*)gemm_db<1,1>,
                         cudaFuncAttributeMaxDynamicSharedMemorySize, GEMM_SMEM_BYTES);
    cudaFuncSetAttribute((const void*)qkv_db,
                         cudaFuncAttributeMaxDynamicSharedMemorySize, GEMM_SMEM_BYTES);

    dim3 blk(256);
    dim3 tblk(32, 8);

    // weight transposes (tf32-rounded, n-major) + hs/dist conversion
    transpose_tf<<<dim3(HID / 32, HID / 32), tblk>>>(Wq,  wqt,  HID, HID);
    transpose_tf<<<dim3(HID / 32, HID / 32), tblk>>>(Wk,  wkt,  HID, HID);
    transpose_tf<<<dim3(HID / 32, HID / 32), tblk>>>(Wv,  wvt,  HID, HID);
    transpose_tf<<<dim3(HID / 32, HID / 32), tblk>>>(Wo,  wot,  HID, HID);
    transpose_tf<<<dim3(FFDIM / 32, HID / 32), tblk>>>(Wi,  wit,  HID, FFDIM);
    transpose_tf<<<dim3(HID / 32, FFDIM / 32), tblk>>>(Wo2, wo2t, FFDIM, HID);
    cvt_hs_dist<<<(CVT2_TOTAL + 255) / 256, blk>>>(hs, dist, hs_tf, disth);

    dim3 g_qkv(HID / 128, NTOK / 128, 3);
    dim3 g_1024(HID / 128, NTOK / 128);
    dim3 g_ff1(FFDIM / 128, NTOK / 128);

    qkv_db<<<g_qkv, blk, GEMM_SMEM_BYTES>>>(hs_tf, wqt, wkt, wvt, bq, bk, bv,
                                            qh, kh, vh);

    attn_tc<<<dim3(SEQ / 64, BATCH * NHEAD), blk, ATTN_SMEM_BYTES>>>(
        qh, kh, vh, disth, mask, hm, ctx);

    gemm_db<0,0><<<g_1024, blk, GEMM_SMEM_BYTES>>>(ctx, wot, bo, tmp, NTOK, HID, HID);
    ln_residual<<<NTOK, blk>>>(tmp, hs, ln1g, ln1b, attnout, attnout_tf);

    gemm_db<1,1><<<g_ff1, blk, GEMM_SMEM_BYTES>>>(attnout_tf, wit, bi, inter,
                                                  NTOK, FFDIM, HID);
    gemm_db<0,0><<<g_1024, blk, GEMM_SMEM_BYTES>>>(inter, wo2t, bo2, tmp,
                                                   NTOK, HID, FFDIM);
    ln_residual<<<NTOK, blk>>>(tmp, attnout, ln2g, ln2b, out, nullptr);
}

// round 15
// speedup vs baseline: 1.4366x; 1.4366x over previous
#include <cuda_runtime.h>
#include <cuda_bf16.h>
#include <cuda_fp16.h>
#include <math.h>
#include <stdint.h>

#define HID    1024
#define FFDIM  4096
#define NHEAD  16
#define HD     64
#define BATCH  4
#define SEQ    1024
#define NTOK   (BATCH*SEQ)
#define MAXPOS 1024

// ---------------- scratch ----------------
__device__ __nv_bfloat16 g_qh[NTOK * HID];
__device__ __nv_bfloat16 g_kh[NTOK * HID];
__device__ __nv_bfloat16 g_vh[NTOK * HID];
__device__ __nv_bfloat16 g_disth[(2 * MAXPOS - 1) * HD];
__device__ __half g_hs_h[NTOK * HID];
__device__ __half g_wq_h[HID * HID];
__device__ __half g_wk_h[HID * HID];
__device__ __half g_wv_h[HID * HID];
__device__ __half g_wo_h[HID * HID];
__device__ __half g_wi_h[HID * FFDIM];
__device__ __half g_wo2_h[FFDIM * HID];
__device__ __half g_ctx_h[NTOK * HID];
__device__ __half g_attnout_h[NTOK * HID];
__device__ __half g_inter_h[NTOK * FFDIM];
__device__ float g_tmp[NTOK * HID];
__device__ float g_attnout[NTOK * HID];

// ---------------- helpers ----------------
__device__ __forceinline__ uint32_t pack_bf2(float x, float y) {
    __nv_bfloat162 h = __floats2bfloat162_rn(x, y);
    return *(uint32_t*)&h;
}
__device__ __forceinline__ uint32_t pack_hf2(float x, float y) {
    __half2 h = __floats2half2_rn(x, y);
    return *(uint32_t*)&h;
}

__device__ __forceinline__ uint32_t smem_u32(const void* p) {
    return (uint32_t)__cvta_generic_to_shared(p);
}

__device__ __forceinline__ void mma_bf16(float c[4], const uint32_t a[4],
                                         const uint32_t b[2]) {
    asm volatile(
        "mma.sync.aligned.m16n8k16.row.col.f32.bf16.bf16.f32 "
        "{%0,%1,%2,%3}, {%4,%5,%6,%7}, {%8,%9}, {%0,%1,%2,%3};"
        : "+f"(c[0]), "+f"(c[1]), "+f"(c[2]), "+f"(c[3])
        : "r"(a[0]), "r"(a[1]), "r"(a[2]), "r"(a[3]), "r"(b[0]), "r"(b[1]));
}

__device__ __forceinline__ void mma_f16(float c[4], const uint32_t a[4],
                                        const uint32_t b[2]) {
    asm volatile(
        "mma.sync.aligned.m16n8k16.row.col.f32.f16.f16.f32 "
        "{%0,%1,%2,%3}, {%4,%5,%6,%7}, {%8,%9}, {%0,%1,%2,%3};"
        : "+f"(c[0]), "+f"(c[1]), "+f"(c[2]), "+f"(c[3])
        : "r"(a[0]), "r"(a[1]), "r"(a[2]), "r"(a[3]), "r"(b[0]), "r"(b[1]));
}

__device__ __forceinline__ void ldsm_x4(uint32_t* r, uint32_t a) {
    asm volatile("ldmatrix.sync.aligned.m8n8.x4.shared.b16 {%0,%1,%2,%3}, [%4];"
        : "=r"(r[0]), "=r"(r[1]), "=r"(r[2]), "=r"(r[3]) : "r"(a));
}
__device__ __forceinline__ void ldsm_x2(uint32_t* r, uint32_t a) {
    asm volatile("ldmatrix.sync.aligned.m8n8.x2.shared.b16 {%0,%1}, [%2];"
        : "=r"(r[0]), "=r"(r[1]) : "r"(a));
}
__device__ __forceinline__ void ldsm_x2t(uint32_t* r, uint32_t a) {
    asm volatile("ldmatrix.sync.aligned.m8n8.x2.trans.shared.b16 {%0,%1}, [%2];"
        : "=r"(r[0]), "=r"(r[1]) : "r"(a));
}

__device__ __forceinline__ void cp16(void* smem, const void* gmem) {
    uint32_t s = (uint32_t)__cvta_generic_to_shared(smem);
    asm volatile("cp.async.cg.shared.global [%0], [%1], 16;" :: "r"(s), "l"(gmem));
}
#define CP_COMMIT() asm volatile("cp.async.commit_group;")
#define CP_WAIT0()  asm volatile("cp.async.wait_group 0;")

// ---------------- fused conversion: weights/hs -> fp16, dist -> bf16 ---------
// float4 units: seg1 = 4x262144 (Wq,Wk,Wv,Wo); seg2 = 3x1048576 (Wi,Wo2,hs);
// seg3 = 32752 (dist).
#define CVT_SEG1 1048576
#define CVT_SEG2 (CVT_SEG1 + 3145728)
#define CVT_TOTAL (CVT_SEG2 + 32752)

__global__ void __launch_bounds__(256) fused_cvt_k(
    const float* __restrict__ Wq, const float* __restrict__ Wk,
    const float* __restrict__ Wv, const float* __restrict__ Wo,
    const float* __restrict__ Wi, const float* __restrict__ Wo2,
    const float* __restrict__ hs, const float* __restrict__ dist,
    __half* __restrict__ wq, __half* __restrict__ wk,
    __half* __restrict__ wv, __half* __restrict__ wo,
    __half* __restrict__ wi, __half* __restrict__ wo2,
    __half* __restrict__ hs_h, __nv_bfloat16* __restrict__ disth)
{
    int idx = blockIdx.x * blockDim.x + threadIdx.x;
    if (idx < CVT_SEG1) {
        const int which = idx >> 18;
        const int rel   = idx & 262143;
        const float* in = (which == 0) ? Wq : (which == 1) ? Wk
                         : (which == 2) ? Wv : Wo;
        __half* out     = (which == 0) ? wq : (which == 1) ? wk
                         : (which == 2) ? wv : wo;
        float4 v = ((const float4*)in)[rel];
        ((uint2*)out)[rel] = make_uint2(pack_hf2(v.x, v.y), pack_hf2(v.z, v.w));
    } else if (idx < CVT_SEG2) {
        const int j     = idx - CVT_SEG1;
        const int which = j >> 20;
        const int rel   = j & 1048575;
        const float* in = (which == 0) ? Wi : (which == 1) ? Wo2 : hs;
        __half* out     = (which == 0) ? wi : (which == 1) ? wo2 : hs_h;
        float4 v = ((const float4*)in)[rel];
        ((uint2*)out)[rel] = make_uint2(pack_hf2(v.x, v.y), pack_hf2(v.z, v.w));
    } else if (idx < CVT_TOTAL) {
        const int rel = idx - CVT_SEG2;
        float4 v = ((const float4*)dist)[rel];
        ((uint2*)disth)[rel] = make_uint2(pack_bf2(v.x, v.y), pack_bf2(v.z, v.w));
    }
}

// ---------------- fp16 GEMM: ldmatrix + m16n8k16 (R12-proven structure) ------
// 256 thr, 8 warps (2x4), warp tile 64x32, CTA 128x128, BK=32.
// A [M][K] row-major fp16; B [K][N] row-major fp16.
// OUT: 0 = fp32, 1 = bf16, 2 = fp16.
#define HA(s,r,c) ((( (s)*128 + (r) )*40) + (c))
#define HB(s,r,c) ((( (s)*32  + (r) )*136) + (c))
#define GEMM_HF_SMEM ((2*128*40 + 2*32*136) * 2)

template <int GELU, int OUT>
__device__ __forceinline__ void gemm_hf_body(
    const __half* __restrict__ A, const __half* __restrict__ Bm,
    const float* __restrict__ bias, void* __restrict__ Cout,
    int M, int N, int K, __half* sm)
{
    __half* As = sm;
    __half* Bs = sm + 2 * 128 * 40;

    const int tid = threadIdx.x;
    const int w   = tid >> 5;
    const int l   = tid & 31;
    const int wr  = w >> 2;
    const int wc  = w & 3;
    const int m0  = blockIdx.y * 128;
    const int n0  = blockIdx.x * 128;
    const int g   = l >> 2;
    const int t4  = l & 3;

    const int ar = tid >> 1;                 // 0..127
    const int ac = (tid & 1) << 3;           // 0 or 8 (second cp at +16)
    const int br = tid >> 3;                 // 0..31
    const int bc = (tid & 7) << 3;           // 0..56 (second cp at +64)

    const int lr = l & 15;
    const int lc = (l >> 4) << 3;

    float c[4][4][4];
#pragma unroll
    for (int mi = 0; mi < 4; mi++)
#pragma unroll
        for (int ni = 0; ni < 4; ni++)
#pragma unroll
            for (int r = 0; r < 4; r++) c[mi][ni][r] = 0.f;

    cp16(&As[HA(0, ar, ac)],      &A[(size_t)(m0 + ar) * K + ac]);
    cp16(&As[HA(0, ar, ac + 16)], &A[(size_t)(m0 + ar) * K + ac + 16]);
    cp16(&Bs[HB(0, br, bc)],      &Bm[(size_t)br * N + n0 + bc]);
    cp16(&Bs[HB(0, br, bc + 64)], &Bm[(size_t)br * N + n0 + bc + 64]);
    CP_COMMIT();

    for (int k0 = 0; k0 < K; k0 += 32) {
        const int s = (k0 >> 5) & 1;
        CP_WAIT0();
        __syncthreads();
        if (k0 + 32 < K) {
            const int ns = s ^ 1;
            const int nk = k0 + 32;
            cp16(&As[HA(ns, ar, ac)],      &A[(size_t)(m0 + ar) * K + nk + ac]);
            cp16(&As[HA(ns, ar, ac + 16)], &A[(size_t)(m0 + ar) * K + nk + ac + 16]);
            cp16(&Bs[HB(ns, br, bc)],      &Bm[(size_t)(nk + br) * N + n0 + bc]);
            cp16(&Bs[HB(ns, br, bc + 64)], &Bm[(size_t)(nk + br) * N + n0 + bc + 64]);
            CP_COMMIT();
        }

        const uint32_t aB = smem_u32(&As[HA(s, 0, 0)]) +
                            ((wr * 64 + lr) * 40 + lc) * 2;
        const uint32_t bB = smem_u32(&Bs[HB(s, lr, 0)]);

#pragma unroll
        for (int kk = 0; kk < 2; kk++) {
            const int kb = kk * 16;
            uint32_t a[4][4], b[4][2];
#pragma unroll
            for (int mi = 0; mi < 4; mi++)
                ldsm_x4(a[mi], aB + (mi * 16 * 40 + kb) * 2);
#pragma unroll
            for (int ni = 0; ni < 4; ni++) {
                const int ncol = wc * 32 + ni * 8;
                ldsm_x2t(b[ni], bB + (kb * 136 + ncol) * 2);
            }
#pragma unroll
            for (int mi = 0; mi < 4; mi++)
#pragma unroll
                for (int ni = 0; ni < 4; ni++)
                    mma_f16(c[mi][ni], a[mi], b[ni]);
        }
    }

#pragma unroll
    for (int mi = 0; mi < 4; mi++) {
#pragma unroll
        for (int ni = 0; ni < 4; ni++) {
            const int row = m0 + wr * 64 + mi * 16 + g;
            const int col = n0 + wc * 32 + ni * 8 + t4 * 2;
            const float b0 = bias[col], b1 = bias[col + 1];
            float v0 = c[mi][ni][0] + b0;
            float v1 = c[mi][ni][1] + b1;
            float v2 = c[mi][ni][2] + b0;
            float v3 = c[mi][ni][3] + b1;
            if (GELU) {
                v0 = 0.5f * v0 * (1.0f + erff(v0 * 0.70710678118654752f));
                v1 = 0.5f * v1 * (1.0f + erff(v1 * 0.70710678118654752f));
                v2 = 0.5f * v2 * (1.0f + erff(v2 * 0.70710678118654752f));
                v3 = 0.5f * v3 * (1.0f + erff(v3 * 0.70710678118654752f));
            }
            if (OUT == 1) {
                __nv_bfloat16* C = (__nv_bfloat16*)Cout;
                *(uint32_t*)&C[(size_t)row * N + col]       = pack_bf2(v0, v1);
                *(uint32_t*)&C[(size_t)(row + 8) * N + col] = pack_bf2(v2, v3);
            } else if (OUT == 2) {
                __half* C = (__half*)Cout;
                *(uint32_t*)&C[(size_t)row * N + col]       = pack_hf2(v0, v1);
                *(uint32_t*)&C[(size_t)(row + 8) * N + col] = pack_hf2(v2, v3);
            } else {
                float* C = (float*)Cout;
                *(float2*)&C[(size_t)row * N + col]       = make_float2(v0, v1);
                *(float2*)&C[(size_t)(row + 8) * N + col] = make_float2(v2, v3);
            }
        }
    }
}

template <int GELU, int OUT>
__global__ void __launch_bounds__(256) gemm_hf(
    const __half* __restrict__ A, const __half* __restrict__ Bm,
    const float* __restrict__ bias, void* __restrict__ Cout,
    int M, int N, int K)
{
    extern __shared__ __half smh[];
    gemm_hf_body<GELU, OUT>(A, Bm, bias, Cout, M, N, K, smh);
}

__global__ void __launch_bounds__(256) qkv_hf(
    const __half* __restrict__ A,
    const __half* __restrict__ W0, const __half* __restrict__ W1,
    const __half* __restrict__ W2,
    const float* __restrict__ b0, const float* __restrict__ b1,
    const float* __restrict__ b2,
    __nv_bfloat16* __restrict__ o0, __nv_bfloat16* __restrict__ o1,
    __nv_bfloat16* __restrict__ o2)
{
    extern __shared__ __half smh[];
    const int z = blockIdx.z;
    const __half* W = (z == 0) ? W0 : (z == 1) ? W1 : W2;
    const float* bb = (z == 0) ? b0 : (z == 1) ? b1 : b2;
    __nv_bfloat16* O = (z == 0) ? o0 : (z == 1) ? o1 : o2;
    gemm_hf_body<0, 1>(A, W, bb, O, NTOK, HID, HID, smh);
}

// ---------------- LayerNorm(x + res) * g + b, optional fp16 copy -------------
__global__ void __launch_bounds__(256) ln_residual(
    const float* __restrict__ x, const float* __restrict__ res,
    const float* __restrict__ g, const float* __restrict__ b,
    float* __restrict__ out, __half* __restrict__ out_h)
{
    __shared__ float red[8];
    const int row = blockIdx.x;
    const int tid = threadIdx.x;
    const size_t base = (size_t)row * HID + tid * 4;

    float4 xv = *(const float4*)&x[base];
    float4 rv = *(const float4*)&res[base];
    float v0 = xv.x + rv.x, v1 = xv.y + rv.y, v2 = xv.z + rv.z, v3 = xv.w + rv.w;

    float s = v0 + v1 + v2 + v3;
#pragma unroll
    for (int o = 16; o; o >>= 1) s += __shfl_xor_sync(0xffffffffu, s, o);
    if ((tid & 31) == 0) red[tid >> 5] = s;
    __syncthreads();
    if (tid < 8) {
        s = red[tid];
#pragma unroll
        for (int o = 4; o; o >>= 1) s += __shfl_xor_sync(0xffu, s, o, 8);
        if (tid == 0) red[0] = s;
    }
    __syncthreads();
    const float mean = red[0] * (1.0f / HID);
    __syncthreads();

    float d0 = v0 - mean, d1 = v1 - mean, d2 = v2 - mean, d3 = v3 - mean;
    float vs = d0 * d0 + d1 * d1 + d2 * d2 + d3 * d3;
#pragma unroll
    for (int o = 16; o; o >>= 1) vs += __shfl_xor_sync(0xffffffffu, vs, o);
    if ((tid & 31) == 0) red[tid >> 5] = vs;
    __syncthreads();
    if (tid < 8) {
        vs = red[tid];
#pragma unroll
        for (int o = 4; o; o >>= 1) vs += __shfl_xor_sync(0xffu, vs, o, 8);
        if (tid == 0) red[0] = vs;
    }
    __syncthreads();
    const float inv = rsqrtf(red[0] * (1.0f / HID) + 1e-12f);

    float4 gv = *(const float4*)&g[tid * 4];
    float4 bv = *(const float4*)&b[tid * 4];
    float4 ov;
    ov.x = d0 * inv * gv.x + bv.x;
    ov.y = d1 * inv * gv.y + bv.y;
    ov.z = d2 * inv * gv.z + bv.z;
    ov.w = d3 * inv * gv.w + bv.w;
    *(float4*)&out[base] = ov;
    if (out_h) {
        *(uint2*)&out_h[base] =
            make_uint2(pack_hf2(ov.x, ov.y), pack_hf2(ov.z, ov.w));
    }
}

// ---------------- bf16 TC attention (R10/R13-proven; ctx output fp16) --------
#define HST 72
#define BSTH 132
#define ATTN_SMEM_BYTES 108544

__global__ void __launch_bounds__(256, 2) attn_tc(
    const __nv_bfloat16* __restrict__ Q, const __nv_bfloat16* __restrict__ K,
    const __nv_bfloat16* __restrict__ V, const __nv_bfloat16* __restrict__ disth,
    const float* __restrict__ mask, const float* __restrict__ hm,
    __half* __restrict__ ctx)
{
    extern __shared__ char smb[];
    __nv_bfloat16* Qh  = (__nv_bfloat16*)smb;
    __nv_bfloat16* Kh  = Qh + 64 * HST;
    __nv_bfloat16* Er  = Kh + 2 * 64 * HST;
    __nv_bfloat16* Vh  = Er + 128 * HST;
    __nv_bfloat16* B1h = Vh + 2 * 64 * HST;
    __nv_bfloat16* B2h = B1h + 64 * BSTH;
    __nv_bfloat16* Ph  = B2h + 64 * BSTH;
    float*         Rmax = (float*)(Ph + 64 * HST);
    float*         Rsum = Rmax + 128;

    const int tid = threadIdx.x;
    const int w   = tid >> 5;
    const int wm  = w & 3;
    const int wn  = w >> 2;
    const int l   = tid & 31;
    const int g   = l >> 2;
    const int t4  = l & 3;
    const int bh  = blockIdx.y;
    const int b   = bh >> 4;
    const int h   = bh & 15;
    const int l0  = blockIdx.x * 64;

    const int li0 = 16 * wm + g;
    const int li1 = li0 + 8;

    const int arow = 16 * wm + (l & 15);
    const int acol = (l >> 4) << 3;
    const uint32_t aQ = smem_u32(&Qh[arow * HST + acol]);
    const uint32_t aP = smem_u32(&Ph[arow * HST + acol]);
    const uint32_t aKb[2] = { smem_u32(&Kh[arow * HST + acol]),
                              smem_u32(&Kh[64 * HST + arow * HST + acol]) };
    const int brow = l & 7;
    const int bcol = ((l >> 3) & 1) << 3;
    const uint32_t bKb[2] = { smem_u32(&Kh[brow * HST + bcol]),
                              smem_u32(&Kh[64 * HST + brow * HST + bcol]) };
    const uint32_t bEbase = smem_u32(Er) + bcol * 2;
    const uint32_t bVb[2] = { smem_u32(&Vh[(l & 15) * HST]),
                              smem_u32(&Vh[64 * HST + (l & 15) * HST]) };

    const __nv_bfloat16* Qg = Q + (size_t)(b * SEQ + l0) * HID + h * HD;
    const __nv_bfloat16* Kg = K + (size_t)(b * SEQ) * HID + h * HD;
    const __nv_bfloat16* Vg = V + (size_t)(b * SEQ) * HID + h * HD;
    const float* mg = mask + b * SEQ;

    for (int idx = tid; idx < 512; idx += 256) {
        int r = idx >> 3, c8 = (idx & 7) << 3;
        cp16(&Qh[r * HST + c8], &Qg[(size_t)r * HID + c8]);
    }
    {
        const int dbase0 = l0 + 960;
        for (int idx = tid; idx < 1024; idx += 256) {
            int r = idx >> 3, c8 = (idx & 7) << 3;
            int row = dbase0 + r;
            int rowc = row > 2046 ? 2046 : row;
            cp16(&Er[(row & 127) * HST + c8], &disth[(size_t)rowc * HD + c8]);
        }
        for (int idx = tid; idx < 512; idx += 256) {
            int r = idx >> 3, c8 = (idx & 7) << 3;
            cp16(&Kh[r * HST + c8], &Kg[(size_t)r * HID + c8]);
            cp16(&Vh[r * HST + c8], &Vg[(size_t)r * HID + c8]);
        }
    }
    CP_COMMIT();
    CP_WAIT0();
    __syncthreads();

    uint32_t aq[4][4];
#pragma unroll
    for (int kk = 0; kk < 4; kk++) ldsm_x4(aq[kk], aQ + kk * 32);

    float O[4][4];
#pragma unroll
    for (int ni = 0; ni < 4; ni++)
#pragma unroll
        for (int r = 0; r < 4; r++) O[ni][r] = 0.f;
    float mrow[2] = {-1e30f, -1e30f};
    float lrow[2] = {0.f, 0.f};

    const int j0 = 48 - 16 * wm + wn * 40;

    for (int rt = 0; rt < 16; rt++) {
        const int r0 = rt * 64;
        const int dbase = l0 - r0 + 960;
        const int buf = rt & 1;
        if (rt) {
            CP_WAIT0();
            __syncthreads();
        }

        if (rt < 15) {
            const int nbuf = buf ^ 1;
            const int nr0 = r0 + 64;
            for (int idx = tid; idx < 512; idx += 256) {
                int r = idx >> 3, c8 = (idx & 7) << 3;
                cp16(&Kh[nbuf * 64 * HST + r * HST + c8],
                     &Kg[(size_t)(nr0 + r) * HID + c8]);
                cp16(&Vh[nbuf * 64 * HST + r * HST + c8],
                     &Vg[(size_t)(nr0 + r) * HID + c8]);
            }
            CP_COMMIT();
        }

        uint32_t ak[4][4];
#pragma unroll
        for (int kk = 0; kk < 4; kk++) ldsm_x4(ak[kk], aKb[buf] + kk * 32);

        {
            float c[5][4];
#pragma unroll
            for (int ni = 0; ni < 5; ni++)
#pragma unroll
                for (int r = 0; r < 4; r++) c[ni][r] = 0.f;
#pragma unroll
            for (int kk = 0; kk < 4; kk++) {
#pragma unroll
                for (int ni = 0; ni < 5; ni++) {
                    const int j = j0 + ni * 8;
                    const int slot = (dbase + j + brow) & 127;
                    uint32_t bf[2];
                    ldsm_x2(bf, bEbase + slot * (HST * 2) + kk * 32);
                    mma_bf16(c[ni], ak[kk], bf);
                }
            }
#pragma unroll
            for (int ni = 0; ni < 5; ni++) {
                const int col = j0 + ni * 8 + 2 * t4;
                *(uint32_t*)&B2h[li0 * BSTH + col] = pack_bf2(c[ni][0], c[ni][1]);
                *(uint32_t*)&B2h[li1 * BSTH + col] = pack_bf2(c[ni][2], c[ni][3]);
            }
        }

        const int nblk = (rt == 0) ? 2 : 1;
        for (int blk = 0; blk < nblk; blk++) {
            const int base = (dbase + 64 * blk) & 127;
            float c[4][4];
#pragma unroll
            for (int ni = 0; ni < 4; ni++)
#pragma unroll
                for (int r = 0; r < 4; r++) c[ni][r] = 0.f;
#pragma unroll
            for (int kk = 0; kk < 4; kk++) {
#pragma unroll
                for (int ni = 0; ni < 4; ni++) {
                    const int slot = base + wn * 32 + ni * 8 + brow;
                    uint32_t bf[2];
                    ldsm_x2(bf, bEbase + slot * (HST * 2) + kk * 32);
                    mma_bf16(c[ni], aq[kk], bf);
                }
            }
#pragma unroll
            for (int ni = 0; ni < 4; ni++) {
                const int col = base + wn * 32 + ni * 8 + 2 * t4;
                *(uint32_t*)&B1h[li0 * BSTH + col] = pack_bf2(c[ni][0], c[ni][1]);
                *(uint32_t*)&B1h[li1 * BSTH + col] = pack_bf2(c[ni][2], c[ni][3]);
            }
        }

        float cS[4][4];
#pragma unroll
        for (int ni = 0; ni < 4; ni++)
#pragma unroll
            for (int r = 0; r < 4; r++) cS[ni][r] = 0.f;
#pragma unroll
        for (int kk = 0; kk < 4; kk++) {
#pragma unroll
            for (int ni = 0; ni < 4; ni++) {
                const int ncol = wn * 32 + ni * 8;
                uint32_t bf[2];
                ldsm_x2(bf, bKb[buf] + (ncol * HST) * 2 + kk * 32);
                mma_bf16(cS[ni], aq[kk], bf);
            }
        }
        __syncthreads();

        if (rt < 15) {
            const int ndbase = dbase - 64;
            for (int idx = tid; idx < 512; idx += 256) {
                int r = idx >> 3, c8 = (idx & 7) << 3;
                int row = ndbase + r;
                cp16(&Er[(row & 127) * HST + c8], &disth[(size_t)row * HD + c8]);
            }
            CP_COMMIT();
        }

        const int dofs = dbase + 63;
        float vmax0 = -1e30f, vmax1 = -1e30f;
#pragma unroll
        for (int ni = 0; ni < 4; ni++) {
#pragma unroll
            for (int e = 0; e < 2; e++) {
                const int rj = wn * 32 + ni * 8 + 2 * t4 + e;
                const float mv = mg[r0 + rj];
                const int s0 = (dofs + li0 - rj) & 127;
                const int s1 = (dofs + li1 - rj) & 127;
                const int ib0 = li0 - rj + 63;
                const int ib1 = li1 - rj + 63;
                float b1a = __bfloat162float(B1h[li0 * BSTH + s0]);
                float b1b = __bfloat162float(B1h[li1 * BSTH + s1]);
                float b2a = __bfloat162float(B2h[rj * BSTH + ib0]);
                float b2b = __bfloat162float(B2h[rj * BSTH + ib1]);
                float v0 = (cS[ni][e]     + b1a + b2a) * 0.125f + mv;
                float v1 = (cS[ni][2 + e] + b1b + b2b) * 0.125f + mv;
                cS[ni][e]     = v0;
                cS[ni][2 + e] = v1;
                vmax0 = fmaxf(vmax0, v0);
                vmax1 = fmaxf(vmax1, v1);
            }
        }
        vmax0 = fmaxf(vmax0, __shfl_xor_sync(0xffffffffu, vmax0, 1));
        vmax0 = fmaxf(vmax0, __shfl_xor_sync(0xffffffffu, vmax0, 2));
        vmax1 = fmaxf(vmax1, __shfl_xor_sync(0xffffffffu, vmax1, 1));
        vmax1 = fmaxf(vmax1, __shfl_xor_sync(0xffffffffu, vmax1, 2));
        if (t4 == 0) {
            Rmax[wn * 64 + li0] = vmax0;
            Rmax[wn * 64 + li1] = vmax1;
        }
        __syncthreads();
        vmax0 = fmaxf(vmax0, Rmax[(wn ^ 1) * 64 + li0]);
        vmax1 = fmaxf(vmax1, Rmax[(wn ^ 1) * 64 + li1]);

        const float nm0 = fmaxf(mrow[0], vmax0);
        const float nm1 = fmaxf(mrow[1], vmax1);
        const float corr0 = __expf(mrow[0] - nm0);
        const float corr1 = __expf(mrow[1] - nm1);

        float ts0 = 0.f, ts1 = 0.f;
#pragma unroll
        for (int ni = 0; ni < 4; ni++) {
            const int cj = wn * 32 + ni * 8 + 2 * t4;
            float p00 = __expf(cS[ni][0] - nm0);
            float p01 = __expf(cS[ni][1] - nm0);
            float p10 = __expf(cS[ni][2] - nm1);
            float p11 = __expf(cS[ni][3] - nm1);
            *(uint32_t*)&Ph[li0 * HST + cj] = pack_bf2(p00, p01);
            *(uint32_t*)&Ph[li1 * HST + cj] = pack_bf2(p10, p11);
            ts0 += p00 + p01;
            ts1 += p10 + p11;
        }
        ts0 += __shfl_xor_sync(0xffffffffu, ts0, 1);
        ts0 += __shfl_xor_sync(0xffffffffu, ts0, 2);
        ts1 += __shfl_xor_sync(0xffffffffu, ts1, 1);
        ts1 += __shfl_xor_sync(0xffffffffu, ts1, 2);
        if (t4 == 0) {
            Rsum[wn * 64 + li0] = ts0;
            Rsum[wn * 64 + li1] = ts1;
        }
        __syncthreads();
        ts0 += Rsum[(wn ^ 1) * 64 + li0];
        ts1 += Rsum[(wn ^ 1) * 64 + li1];

        lrow[0] = lrow[0] * corr0 + ts0;
        lrow[1] = lrow[1] * corr1 + ts1;
        mrow[0] = nm0;
        mrow[1] = nm1;
#pragma unroll
        for (int ni = 0; ni < 4; ni++) {
            O[ni][0] *= corr0;
            O[ni][1] *= corr0;
            O[ni][2] *= corr1;
            O[ni][3] *= corr1;
        }

#pragma unroll
        for (int kk = 0; kk < 4; kk++) {
            const int kb = kk * 16;
            uint32_t ap[4];
            ldsm_x4(ap, aP + kk * 32);
#pragma unroll
            for (int ni = 0; ni < 4; ni++) {
                const int nbase = wn * 32 + ni * 8;
                uint32_t bf[2];
                ldsm_x2t(bf, bVb[buf] + (kb * HST + nbase) * 2);
                mma_bf16(O[ni], ap, bf);
            }
        }
    }

    const float hscale = hm[h];
    const float inv0 = hscale / lrow[0];
    const float inv1 = hscale / lrow[1];
#pragma unroll
    for (int ni = 0; ni < 4; ni++) {
        const int col = h * HD + wn * 32 + ni * 8 + 2 * t4;
        const size_t row0g = (size_t)(b * SEQ + l0 + li0) * HID + col;
        const size_t row1g = (size_t)(b * SEQ + l0 + li1) * HID + col;
        *(uint32_t*)&ctx[row0g] = pack_hf2(O[ni][0] * inv0, O[ni][1] * inv0);
        *(uint32_t*)&ctx[row1g] = pack_hf2(O[ni][2] * inv1, O[ni][3] * inv1);
    }
}

// ---------------- launch ----------------
extern "C" void kernel_launch(void* const* d_in, const int* in_sizes, int n_in,
                              void* d_out, int out_size)
{
    const float* hs   = (const float*)d_in[0];
    const float* mask = (const float*)d_in[1];
    const float* hm   = (const float*)d_in[2];
    const float* Wq   = (const float*)d_in[3];
    const float* bq   = (const float*)d_in[4];
    const float* Wk   = (const float*)d_in[5];
    const float* bk   = (const float*)d_in[6];
    const float* Wv   = (const float*)d_in[7];
    const float* bv   = (const float*)d_in[8];
    const float* dist = (const float*)d_in[9];
    const float* Wo   = (const float*)d_in[10];
    const float* bo   = (const float*)d_in[11];
    const float* ln1g = (const float*)d_in[12];
    const float* ln1b = (const float*)d_in[13];
    const float* Wi   = (const float*)d_in[14];
    const float* bi   = (const float*)d_in[15];
    const float* Wo2  = (const float*)d_in[16];
    const float* bo2  = (const float*)d_in[17];
    const float* ln2g = (const float*)d_in[18];
    const float* ln2b = (const float*)d_in[19];
    float* out = (float*)d_out;

    __nv_bfloat16 *qh, *kh, *vh, *disth;
    __half *hs_h, *wq_h, *wk_h, *wv_h, *wo_h, *wi_h, *wo2_h;
    __half *ctx_h, *attnout_h, *inter_h;
    float *tmp, *attnout;
    cudaGetSymbolAddress((void**)&qh,        g_qh);
    cudaGetSymbolAddress((void**)&kh,        g_kh);
    cudaGetSymbolAddress((void**)&vh,        g_vh);
    cudaGetSymbolAddress((void**)&disth,     g_disth);
    cudaGetSymbolAddress((void**)&hs_h,      g_hs_h);
    cudaGetSymbolAddress((void**)&wq_h,      g_wq_h);
    cudaGetSymbolAddress((void**)&wk_h,      g_wk_h);
    cudaGetSymbolAddress((void**)&wv_h,      g_wv_h);
    cudaGetSymbolAddress((void**)&wo_h,      g_wo_h);
    cudaGetSymbolAddress((void**)&wi_h,      g_wi_h);
    cudaGetSymbolAddress((void**)&wo2_h,     g_wo2_h);
    cudaGetSymbolAddress((void**)&ctx_h,     g_ctx_h);
    cudaGetSymbolAddress((void**)&attnout_h, g_attnout_h);
    cudaGetSymbolAddress((void**)&inter_h,   g_inter_h);
    cudaGetSymbolAddress((void**)&tmp,       g_tmp);
    cudaGetSymbolAddress((void**)&attnout,   g_attnout);

    cudaFuncSetAttribute(attn_tc, cudaFuncAttributeMaxDynamicSharedMemorySize,
                         ATTN_SMEM_BYTES);
    cudaFuncSetAttribute((const void*)gemm_hf<0,0>,
                         cudaFuncAttributeMaxDynamicSharedMemorySize, GEMM_HF_SMEM);
    cudaFuncSetAttribute((const void*)gemm_hf<1,2>,
                         cudaFuncAttributeMaxDynamicSharedMemorySize, GEMM_HF_SMEM);
    cudaFuncSetAttribute((const void*)qkv_hf,
                         cudaFuncAttributeMaxDynamicSharedMemorySize, GEMM_HF_SMEM);

    dim3 blk(256);

    fused_cvt_k<<<(CVT_TOTAL + 255) / 256, blk>>>(
        Wq, Wk, Wv, Wo, Wi, Wo2, hs, dist,
        wq_h, wk_h, wv_h, wo_h, wi_h, wo2_h, hs_h, disth);

    dim3 g_qkv(HID / 128, NTOK / 128, 3);
    dim3 g_1024(HID / 128, NTOK / 128);
    dim3 g_ff1(FFDIM / 128, NTOK / 128);

    qkv_hf<<<g_qkv, blk, GEMM_HF_SMEM>>>(hs_h, wq_h, wk_h, wv_h, bq, bk, bv,
                                         qh, kh, vh);

    attn_tc<<<dim3(SEQ / 64, BATCH * NHEAD), blk, ATTN_SMEM_BYTES>>>(
        qh, kh, vh, disth, mask, hm, ctx_h);

    gemm_hf<0,0><<<g_1024, blk, GEMM_HF_SMEM>>>(ctx_h, wo_h, bo, tmp,
                                                NTOK, HID, HID);
    ln_residual<<<NTOK, blk>>>(tmp, hs, ln1g, ln1b, attnout, attnout_h);

    gemm_hf<1,2><<<g_ff1, blk, GEMM_HF_SMEM>>>(attnout_h, wi_h, bi, inter_h,
                                               NTOK, FFDIM, HID);
    gemm_hf<0,0><<<g_1024, blk, GEMM_HF_SMEM>>>(inter_h, wo2_h, bo2, tmp,
                                                NTOK, HID, FFDIM);
    ln_residual<<<NTOK, blk>>>(tmp, attnout, ln2g, ln2b, out, nullptr);
}

// round 16
// speedup vs baseline: 1.4464x; 1.0068x over previous
#include <cuda_runtime.h>
#include <cuda_bf16.h>
#include <cuda_fp16.h>
#include <math.h>
#include <stdint.h>

#define HID    1024
#define FFDIM  4096
#define NHEAD  16
#define HD     64
#define BATCH  4
#define SEQ    1024
#define NTOK   (BATCH*SEQ)
#define MAXPOS 1024

// ---------------- scratch ----------------
__device__ __nv_bfloat16 g_qh[NTOK * HID];
__device__ __nv_bfloat16 g_kh[NTOK * HID];
__device__ __nv_bfloat16 g_vh[NTOK * HID];
__device__ __nv_bfloat16 g_disth[(2 * MAXPOS - 1) * HD];
__device__ __half g_hs_h[NTOK * HID];
__device__ __half g_wq_h[HID * HID];
__device__ __half g_wk_h[HID * HID];
__device__ __half g_wv_h[HID * HID];
__device__ __half g_wo_h[HID * HID];
__device__ __half g_wi_h[HID * FFDIM];
__device__ __half g_wo2_h[FFDIM * HID];
__device__ __half g_ctx_h[NTOK * HID];
__device__ __half g_attnout_h[NTOK * HID];
__device__ __half g_inter_h[NTOK * FFDIM];
__device__ float g_tmp[NTOK * HID];
__device__ float g_attnout[NTOK * HID];

// ---------------- helpers ----------------
__device__ __forceinline__ uint32_t pack_bf2(float x, float y) {
    __nv_bfloat162 h = __floats2bfloat162_rn(x, y);
    return *(uint32_t*)&h;
}
__device__ __forceinline__ uint32_t pack_hf2(float x, float y) {
    __half2 h = __floats2half2_rn(x, y);
    return *(uint32_t*)&h;
}

__device__ __forceinline__ uint32_t smem_u32(const void* p) {
    return (uint32_t)__cvta_generic_to_shared(p);
}

__device__ __forceinline__ void mma_bf16(float c[4], const uint32_t a[4],
                                         const uint32_t b[2]) {
    asm volatile(
        "mma.sync.aligned.m16n8k16.row.col.f32.bf16.bf16.f32 "
        "{%0,%1,%2,%3}, {%4,%5,%6,%7}, {%8,%9}, {%0,%1,%2,%3};"
        : "+f"(c[0]), "+f"(c[1]), "+f"(c[2]), "+f"(c[3])
        : "r"(a[0]), "r"(a[1]), "r"(a[2]), "r"(a[3]), "r"(b[0]), "r"(b[1]));
}

__device__ __forceinline__ void mma_f16(float c[4], const uint32_t a[4],
                                        const uint32_t b[2]) {
    asm volatile(
        "mma.sync.aligned.m16n8k16.row.col.f32.f16.f16.f32 "
        "{%0,%1,%2,%3}, {%4,%5,%6,%7}, {%8,%9}, {%0,%1,%2,%3};"
        : "+f"(c[0]), "+f"(c[1]), "+f"(c[2]), "+f"(c[3])
        : "r"(a[0]), "r"(a[1]), "r"(a[2]), "r"(a[3]), "r"(b[0]), "r"(b[1]));
}

__device__ __forceinline__ void ldsm_x4(uint32_t* r, uint32_t a) {
    asm volatile("ldmatrix.sync.aligned.m8n8.x4.shared.b16 {%0,%1,%2,%3}, [%4];"
        : "=r"(r[0]), "=r"(r[1]), "=r"(r[2]), "=r"(r[3]) : "r"(a));
}
__device__ __forceinline__ void ldsm_x2(uint32_t* r, uint32_t a) {
    asm volatile("ldmatrix.sync.aligned.m8n8.x2.shared.b16 {%0,%1}, [%2];"
        : "=r"(r[0]), "=r"(r[1]) : "r"(a));
}
__device__ __forceinline__ void ldsm_x2t(uint32_t* r, uint32_t a) {
    asm volatile("ldmatrix.sync.aligned.m8n8.x2.trans.shared.b16 {%0,%1}, [%2];"
        : "=r"(r[0]), "=r"(r[1]) : "r"(a));
}

__device__ __forceinline__ void cp16(void* smem, const void* gmem) {
    uint32_t s = (uint32_t)__cvta_generic_to_shared(smem);
    asm volatile("cp.async.cg.shared.global [%0], [%1], 16;" :: "r"(s), "l"(gmem));
}
#define CP_COMMIT() asm volatile("cp.async.commit_group;")
#define CP_WAIT0()  asm volatile("cp.async.wait_group 0;")

// ---------------- fused conversion: weights/hs -> fp16, dist -> bf16 ---------
#define CVT_SEG1 1048576
#define CVT_SEG2 (CVT_SEG1 + 3145728)
#define CVT_TOTAL (CVT_SEG2 + 32752)

__global__ void __launch_bounds__(256) fused_cvt_k(
    const float* __restrict__ Wq, const float* __restrict__ Wk,
    const float* __restrict__ Wv, const float* __restrict__ Wo,
    const float* __restrict__ Wi, const float* __restrict__ Wo2,
    const float* __restrict__ hs, const float* __restrict__ dist,
    __half* __restrict__ wq, __half* __restrict__ wk,
    __half* __restrict__ wv, __half* __restrict__ wo,
    __half* __restrict__ wi, __half* __restrict__ wo2,
    __half* __restrict__ hs_h, __nv_bfloat16* __restrict__ disth)
{
    int idx = blockIdx.x * blockDim.x + threadIdx.x;
    if (idx < CVT_SEG1) {
        const int which = idx >> 18;
        const int rel   = idx & 262143;
        const float* in = (which == 0) ? Wq : (which == 1) ? Wk
                         : (which == 2) ? Wv : Wo;
        __half* out     = (which == 0) ? wq : (which == 1) ? wk
                         : (which == 2) ? wv : wo;
        float4 v = ((const float4*)in)[rel];
        ((uint2*)out)[rel] = make_uint2(pack_hf2(v.x, v.y), pack_hf2(v.z, v.w));
    } else if (idx < CVT_SEG2) {
        const int j     = idx - CVT_SEG1;
        const int which = j >> 20;
        const int rel   = j & 1048575;
        const float* in = (which == 0) ? Wi : (which == 1) ? Wo2 : hs;
        __half* out     = (which == 0) ? wi : (which == 1) ? wo2 : hs_h;
        float4 v = ((const float4*)in)[rel];
        ((uint2*)out)[rel] = make_uint2(pack_hf2(v.x, v.y), pack_hf2(v.z, v.w));
    } else if (idx < CVT_TOTAL) {
        const int rel = idx - CVT_SEG2;
        float4 v = ((const float4*)dist)[rel];
        ((uint2*)disth)[rel] = make_uint2(pack_bf2(v.x, v.y), pack_bf2(v.z, v.w));
    }
}

// ---------------- fp16 GEMM: BK=64, ldmatrix + m16n8k16 ----------------------
// 256 thr, 8 warps (2x4), warp tile 64x32, CTA 128x128.
// A [M][K] row-major fp16; B [K][N] row-major fp16.
// OUT: 0 = fp32, 1 = bf16, 2 = fp16.
#define HA(s,r,c) ((( (s)*128 + (r) )*72) + (c))
#define HB(s,r,c) ((( (s)*64  + (r) )*136) + (c))
#define STAGEA (128 * 72 * 2)
#define STAGEB (64 * 136 * 2)
#define GEMM_HF_SMEM ((2*128*72 + 2*64*136) * 2)

template <int GELU, int OUT>
__device__ __forceinline__ void gemm_hf_body(
    const __half* __restrict__ A, const __half* __restrict__ Bm,
    const float* __restrict__ bias, void* __restrict__ Cout,
    int M, int N, int K, __half* sm)
{
    __half* As = sm;
    __half* Bs = sm + 2 * 128 * 72;

    const int tid = threadIdx.x;
    const int w   = tid >> 5;
    const int l   = tid & 31;
    const int wr  = w >> 2;
    const int wc  = w & 3;
    const int m0  = blockIdx.y * 128;
    const int n0  = blockIdx.x * 128;
    const int g   = l >> 2;
    const int t4  = l & 3;

    const int ar = tid >> 1;                 // 0..127
    const int ac = (tid & 1) << 3;           // 0 or 8 (cps at +16i)
    const int br = tid >> 3;                 // 0..31 (+32 second row)
    const int bc = (tid & 7) << 3;           // 0..56 (+64 second col)

    const int lr = l & 15;
    const int lc = (l >> 4) << 3;

    float c[4][4][4];
#pragma unroll
    for (int mi = 0; mi < 4; mi++)
#pragma unroll
        for (int ni = 0; ni < 4; ni++)
#pragma unroll
            for (int r = 0; r < 4; r++) c[mi][ni][r] = 0.f;

#pragma unroll
    for (int i = 0; i < 4; i++)
        cp16(&As[HA(0, ar, ac + 16 * i)], &A[(size_t)(m0 + ar) * K + ac + 16 * i]);
    cp16(&Bs[HB(0, br, bc)],           &Bm[(size_t)br * N + n0 + bc]);
    cp16(&Bs[HB(0, br, bc + 64)],      &Bm[(size_t)br * N + n0 + bc + 64]);
    cp16(&Bs[HB(0, br + 32, bc)],      &Bm[(size_t)(br + 32) * N + n0 + bc]);
    cp16(&Bs[HB(0, br + 32, bc + 64)], &Bm[(size_t)(br + 32) * N + n0 + bc + 64]);
    CP_COMMIT();

    for (int k0 = 0; k0 < K; k0 += 64) {
        const int s = (k0 >> 6) & 1;
        CP_WAIT0();
        __syncthreads();
        if (k0 + 64 < K) {
            const int ns = s ^ 1;
            const int nk = k0 + 64;
#pragma unroll
            for (int i = 0; i < 4; i++)
                cp16(&As[HA(ns, ar, ac + 16 * i)],
                     &A[(size_t)(m0 + ar) * K + nk + ac + 16 * i]);
            cp16(&Bs[HB(ns, br, bc)],           &Bm[(size_t)(nk + br) * N + n0 + bc]);
            cp16(&Bs[HB(ns, br, bc + 64)],      &Bm[(size_t)(nk + br) * N + n0 + bc + 64]);
            cp16(&Bs[HB(ns, br + 32, bc)],      &Bm[(size_t)(nk + br + 32) * N + n0 + bc]);
            cp16(&Bs[HB(ns, br + 32, bc + 64)], &Bm[(size_t)(nk + br + 32) * N + n0 + bc + 64]);
            CP_COMMIT();
        }

        const uint32_t aB = smem_u32(As) + s * STAGEA +
                            ((wr * 64 + lr) * 72 + lc) * 2;
        const uint32_t bB = smem_u32(Bs) + s * STAGEB + (lr * 136) * 2;

#pragma unroll
        for (int kk = 0; kk < 4; kk++) {
            const int kb = kk * 16;
            uint32_t a[4][4], b[4][2];
#pragma unroll
            for (int mi = 0; mi < 4; mi++)
                ldsm_x4(a[mi], aB + (mi * 16 * 72 + kb) * 2);
#pragma unroll
            for (int ni = 0; ni < 4; ni++) {
                const int ncol = wc * 32 + ni * 8;
                ldsm_x2t(b[ni], bB + (kb * 136 + ncol) * 2);
            }
#pragma unroll
            for (int mi = 0; mi < 4; mi++)
#pragma unroll
                for (int ni = 0; ni < 4; ni++)
                    mma_f16(c[mi][ni], a[mi], b[ni]);
        }
    }

#pragma unroll
    for (int mi = 0; mi < 4; mi++) {
#pragma unroll
        for (int ni = 0; ni < 4; ni++) {
            const int row = m0 + wr * 64 + mi * 16 + g;
            const int col = n0 + wc * 32 + ni * 8 + t4 * 2;
            const float b0 = bias[col], b1 = bias[col + 1];
            float v0 = c[mi][ni][0] + b0;
            float v1 = c[mi][ni][1] + b1;
            float v2 = c[mi][ni][2] + b0;
            float v3 = c[mi][ni][3] + b1;
            if (GELU) {
                v0 = 0.5f * v0 * (1.0f + erff(v0 * 0.70710678118654752f));
                v1 = 0.5f * v1 * (1.0f + erff(v1 * 0.70710678118654752f));
                v2 = 0.5f * v2 * (1.0f + erff(v2 * 0.70710678118654752f));
                v3 = 0.5f * v3 * (1.0f + erff(v3 * 0.70710678118654752f));
            }
            if (OUT == 1) {
                __nv_bfloat16* C = (__nv_bfloat16*)Cout;
                *(uint32_t*)&C[(size_t)row * N + col]       = pack_bf2(v0, v1);
                *(uint32_t*)&C[(size_t)(row + 8) * N + col] = pack_bf2(v2, v3);
            } else if (OUT == 2) {
                __half* C = (__half*)Cout;
                *(uint32_t*)&C[(size_t)row * N + col]       = pack_hf2(v0, v1);
                *(uint32_t*)&C[(size_t)(row + 8) * N + col] = pack_hf2(v2, v3);
            } else {
                float* C = (float*)Cout;
                *(float2*)&C[(size_t)row * N + col]       = make_float2(v0, v1);
                *(float2*)&C[(size_t)(row + 8) * N + col] = make_float2(v2, v3);
            }
        }
    }
}

template <int GELU, int OUT>
__global__ void __launch_bounds__(256) gemm_hf(
    const __half* __restrict__ A, const __half* __restrict__ Bm,
    const float* __restrict__ bias, void* __restrict__ Cout,
    int M, int N, int K)
{
    extern __shared__ __half smh[];
    gemm_hf_body<GELU, OUT>(A, Bm, bias, Cout, M, N, K, smh);
}

__global__ void __launch_bounds__(256) qkv_hf(
    const __half* __restrict__ A,
    const __half* __restrict__ W0, const __half* __restrict__ W1,
    const __half* __restrict__ W2,
    const float* __restrict__ b0, const float* __restrict__ b1,
    const float* __restrict__ b2,
    __nv_bfloat16* __restrict__ o0, __nv_bfloat16* __restrict__ o1,
    __nv_bfloat16* __restrict__ o2)
{
    extern __shared__ __half smh[];
    const int z = blockIdx.z;
    const __half* W = (z == 0) ? W0 : (z == 1) ? W1 : W2;
    const float* bb = (z == 0) ? b0 : (z == 1) ? b1 : b2;
    __nv_bfloat16* O = (z == 0) ? o0 : (z == 1) ? o1 : o2;
    gemm_hf_body<0, 1>(A, W, bb, O, NTOK, HID, HID, smh);
}

// ---------------- LayerNorm(x + res) * g + b, optional fp16 copy -------------
__global__ void __launch_bounds__(256) ln_residual(
    const float* __restrict__ x, const float* __restrict__ res,
    const float* __restrict__ g, const float* __restrict__ b,
    float* __restrict__ out, __half* __restrict__ out_h)
{
    __shared__ float red[8];
    const int row = blockIdx.x;
    const int tid = threadIdx.x;
    const size_t base = (size_t)row * HID + tid * 4;

    float4 xv = *(const float4*)&x[base];
    float4 rv = *(const float4*)&res[base];
    float v0 = xv.x + rv.x, v1 = xv.y + rv.y, v2 = xv.z + rv.z, v3 = xv.w + rv.w;

    float s = v0 + v1 + v2 + v3;
#pragma unroll
    for (int o = 16; o; o >>= 1) s += __shfl_xor_sync(0xffffffffu, s, o);
    if ((tid & 31) == 0) red[tid >> 5] = s;
    __syncthreads();
    if (tid < 8) {
        s = red[tid];
#pragma unroll
        for (int o = 4; o; o >>= 1) s += __shfl_xor_sync(0xffu, s, o, 8);
        if (tid == 0) red[0] = s;
    }
    __syncthreads();
    const float mean = red[0] * (1.0f / HID);
    __syncthreads();

    float d0 = v0 - mean, d1 = v1 - mean, d2 = v2 - mean, d3 = v3 - mean;
    float vs = d0 * d0 + d1 * d1 + d2 * d2 + d3 * d3;
#pragma unroll
    for (int o = 16; o; o >>= 1) vs += __shfl_xor_sync(0xffffffffu, vs, o);
    if ((tid & 31) == 0) red[tid >> 5] = vs;
    __syncthreads();
    if (tid < 8) {
        vs = red[tid];
#pragma unroll
        for (int o = 4; o; o >>= 1) vs += __shfl_xor_sync(0xffu, vs, o, 8);
        if (tid == 0) red[0] = vs;
    }
    __syncthreads();
    const float inv = rsqrtf(red[0] * (1.0f / HID) + 1e-12f);

    float4 gv = *(const float4*)&g[tid * 4];
    float4 bv = *(const float4*)&b[tid * 4];
    float4 ov;
    ov.x = d0 * inv * gv.x + bv.x;
    ov.y = d1 * inv * gv.y + bv.y;
    ov.z = d2 * inv * gv.z + bv.z;
    ov.w = d3 * inv * gv.w + bv.w;
    *(float4*)&out[base] = ov;
    if (out_h) {
        *(uint2*)&out_h[base] =
            make_uint2(pack_hf2(ov.x, ov.y), pack_hf2(ov.z, ov.w));
    }
}

// ---------------- bf16 TC attention (unchanged from R15) ---------------------
#define HST 72
#define BSTH 132
#define ATTN_SMEM_BYTES 108544

__global__ void __launch_bounds__(256, 2) attn_tc(
    const __nv_bfloat16* __restrict__ Q, const __nv_bfloat16* __restrict__ K,
    const __nv_bfloat16* __restrict__ V, const __nv_bfloat16* __restrict__ disth,
    const float* __restrict__ mask, const float* __restrict__ hm,
    __half* __restrict__ ctx)
{
    extern __shared__ char smb[];
    __nv_bfloat16* Qh  = (__nv_bfloat16*)smb;
    __nv_bfloat16* Kh  = Qh + 64 * HST;
    __nv_bfloat16* Er  = Kh + 2 * 64 * HST;
    __nv_bfloat16* Vh  = Er + 128 * HST;
    __nv_bfloat16* B1h = Vh + 2 * 64 * HST;
    __nv_bfloat16* B2h = B1h + 64 * BSTH;
    __nv_bfloat16* Ph  = B2h + 64 * BSTH;
    float*         Rmax = (float*)(Ph + 64 * HST);
    float*         Rsum = Rmax + 128;

    const int tid = threadIdx.x;
    const int w   = tid >> 5;
    const int wm  = w & 3;
    const int wn  = w >> 2;
    const int l   = tid & 31;
    const int g   = l >> 2;
    const int t4  = l & 3;
    const int bh  = blockIdx.y;
    const int b   = bh >> 4;
    const int h   = bh & 15;
    const int l0  = blockIdx.x * 64;

    const int li0 = 16 * wm + g;
    const int li1 = li0 + 8;

    const int arow = 16 * wm + (l & 15);
    const int acol = (l >> 4) << 3;
    const uint32_t aQ = smem_u32(&Qh[arow * HST + acol]);
    const uint32_t aP = smem_u32(&Ph[arow * HST + acol]);
    const uint32_t aKb[2] = { smem_u32(&Kh[arow * HST + acol]),
                              smem_u32(&Kh[64 * HST + arow * HST + acol]) };
    const int brow = l & 7;
    const int bcol = ((l >> 3) & 1) << 3;
    const uint32_t bKb[2] = { smem_u32(&Kh[brow * HST + bcol]),
                              smem_u32(&Kh[64 * HST + brow * HST + bcol]) };
    const uint32_t bEbase = smem_u32(Er) + bcol * 2;
    const uint32_t bVb[2] = { smem_u32(&Vh[(l & 15) * HST]),
                              smem_u32(&Vh[64 * HST + (l & 15) * HST]) };

    const __nv_bfloat16* Qg = Q + (size_t)(b * SEQ + l0) * HID + h * HD;
    const __nv_bfloat16* Kg = K + (size_t)(b * SEQ) * HID + h * HD;
    const __nv_bfloat16* Vg = V + (size_t)(b * SEQ) * HID + h * HD;
    const float* mg = mask + b * SEQ;

    for (int idx = tid; idx < 512; idx += 256) {
        int r = idx >> 3, c8 = (idx & 7) << 3;
        cp16(&Qh[r * HST + c8], &Qg[(size_t)r * HID + c8]);
    }
    {
        const int dbase0 = l0 + 960;
        for (int idx = tid; idx < 1024; idx += 256) {
            int r = idx >> 3, c8 = (idx & 7) << 3;
            int row = dbase0 + r;
            int rowc = row > 2046 ? 2046 : row;
            cp16(&Er[(row & 127) * HST + c8], &disth[(size_t)rowc * HD + c8]);
        }
        for (int idx = tid; idx < 512; idx += 256) {
            int r = idx >> 3, c8 = (idx & 7) << 3;
            cp16(&Kh[r * HST + c8], &Kg[(size_t)r * HID + c8]);
            cp16(&Vh[r * HST + c8], &Vg[(size_t)r * HID + c8]);
        }
    }
    CP_COMMIT();
    CP_WAIT0();
    __syncthreads();

    uint32_t aq[4][4];
#pragma unroll
    for (int kk = 0; kk < 4; kk++) ldsm_x4(aq[kk], aQ + kk * 32);

    float O[4][4];
#pragma unroll
    for (int ni = 0; ni < 4; ni++)
#pragma unroll
        for (int r = 0; r < 4; r++) O[ni][r] = 0.f;
    float mrow[2] = {-1e30f, -1e30f};
    float lrow[2] = {0.f, 0.f};

    const int j0 = 48 - 16 * wm + wn * 40;

    for (int rt = 0; rt < 16; rt++) {
        const int r0 = rt * 64;
        const int dbase = l0 - r0 + 960;
        const int buf = rt & 1;
        if (rt) {
            CP_WAIT0();
            __syncthreads();
        }

        if (rt < 15) {
            const int nbuf = buf ^ 1;
            const int nr0 = r0 + 64;
            for (int idx = tid; idx < 512; idx += 256) {
                int r = idx >> 3, c8 = (idx & 7) << 3;
                cp16(&Kh[nbuf * 64 * HST + r * HST + c8],
                     &Kg[(size_t)(nr0 + r) * HID + c8]);
                cp16(&Vh[nbuf * 64 * HST + r * HST + c8],
                     &Vg[(size_t)(nr0 + r) * HID + c8]);
            }
            CP_COMMIT();
        }

        uint32_t ak[4][4];
#pragma unroll
        for (int kk = 0; kk < 4; kk++) ldsm_x4(ak[kk], aKb[buf] + kk * 32);

        {
            float c[5][4];
#pragma unroll
            for (int ni = 0; ni < 5; ni++)
#pragma unroll
                for (int r = 0; r < 4; r++) c[ni][r] = 0.f;
#pragma unroll
            for (int kk = 0; kk < 4; kk++) {
#pragma unroll
                for (int ni = 0; ni < 5; ni++) {
                    const int j = j0 + ni * 8;
                    const int slot = (dbase + j + brow) & 127;
                    uint32_t bf[2];
                    ldsm_x2(bf, bEbase + slot * (HST * 2) + kk * 32);
                    mma_bf16(c[ni], ak[kk], bf);
                }
            }
#pragma unroll
            for (int ni = 0; ni < 5; ni++) {
                const int col = j0 + ni * 8 + 2 * t4;
                *(uint32_t*)&B2h[li0 * BSTH + col] = pack_bf2(c[ni][0], c[ni][1]);
                *(uint32_t*)&B2h[li1 * BSTH + col] = pack_bf2(c[ni][2], c[ni][3]);
            }
        }

        const int nblk = (rt == 0) ? 2 : 1;
        for (int blk = 0; blk < nblk; blk++) {
            const int base = (dbase + 64 * blk) & 127;
            float c[4][4];
#pragma unroll
            for (int ni = 0; ni < 4; ni++)
#pragma unroll
                for (int r = 0; r < 4; r++) c[ni][r] = 0.f;
#pragma unroll
            for (int kk = 0; kk < 4; kk++) {
#pragma unroll
                for (int ni = 0; ni < 4; ni++) {
                    const int slot = base + wn * 32 + ni * 8 + brow;
                    uint32_t bf[2];
                    ldsm_x2(bf, bEbase + slot * (HST * 2) + kk * 32);
                    mma_bf16(c[ni], aq[kk], bf);
                }
            }
#pragma unroll
            for (int ni = 0; ni < 4; ni++) {
                const int col = base + wn * 32 + ni * 8 + 2 * t4;
                *(uint32_t*)&B1h[li0 * BSTH + col] = pack_bf2(c[ni][0], c[ni][1]);
                *(uint32_t*)&B1h[li1 * BSTH + col] = pack_bf2(c[ni][2], c[ni][3]);
            }
        }

        float cS[4][4];
#pragma unroll
        for (int ni = 0; ni < 4; ni++)
#pragma unroll
            for (int r = 0; r < 4; r++) cS[ni][r] = 0.f;
#pragma unroll
        for (int kk = 0; kk < 4; kk++) {
#pragma unroll
            for (int ni = 0; ni < 4; ni++) {
                const int ncol = wn * 32 + ni * 8;
                uint32_t bf[2];
                ldsm_x2(bf, bKb[buf] + (ncol * HST) * 2 + kk * 32);
                mma_bf16(cS[ni], aq[kk], bf);
            }
        }
        __syncthreads();

        if (rt < 15) {
            const int ndbase = dbase - 64;
            for (int idx = tid; idx < 512; idx += 256) {
                int r = idx >> 3, c8 = (idx & 7) << 3;
                int row = ndbase + r;
                cp16(&Er[(row & 127) * HST + c8], &disth[(size_t)row * HD + c8]);
            }
            CP_COMMIT();
        }

        const int dofs = dbase + 63;
        float vmax0 = -1e30f, vmax1 = -1e30f;
#pragma unroll
        for (int ni = 0; ni < 4; ni++) {
#pragma unroll
            for (int e = 0; e < 2; e++) {
                const int rj = wn * 32 + ni * 8 + 2 * t4 + e;
                const float mv = mg[r0 + rj];
                const int s0 = (dofs + li0 - rj) & 127;
                const int s1 = (dofs + li1 - rj) & 127;
                const int ib0 = li0 - rj + 63;
                const int ib1 = li1 - rj + 63;
                float b1a = __bfloat162float(B1h[li0 * BSTH + s0]);
                float b1b = __bfloat162float(B1h[li1 * BSTH + s1]);
                float b2a = __bfloat162float(B2h[rj * BSTH + ib0]);
                float b2b = __bfloat162float(B2h[rj * BSTH + ib1]);
                float v0 = (cS[ni][e]     + b1a + b2a) * 0.125f + mv;
                float v1 = (cS[ni][2 + e] + b1b + b2b) * 0.125f + mv;
                cS[ni][e]     = v0;
                cS[ni][2 + e] = v1;
                vmax0 = fmaxf(vmax0, v0);
                vmax1 = fmaxf(vmax1, v1);
            }
        }
        vmax0 = fmaxf(vmax0, __shfl_xor_sync(0xffffffffu, vmax0, 1));
        vmax0 = fmaxf(vmax0, __shfl_xor_sync(0xffffffffu, vmax0, 2));
        vmax1 = fmaxf(vmax1, __shfl_xor_sync(0xffffffffu, vmax1, 1));
        vmax1 = fmaxf(vmax1, __shfl_xor_sync(0xffffffffu, vmax1, 2));
        if (t4 == 0) {
            Rmax[wn * 64 + li0] = vmax0;
            Rmax[wn * 64 + li1] = vmax1;
        }
        __syncthreads();
        vmax0 = fmaxf(vmax0, Rmax[(wn ^ 1) * 64 + li0]);
        vmax1 = fmaxf(vmax1, Rmax[(wn ^ 1) * 64 + li1]);

        const float nm0 = fmaxf(mrow[0], vmax0);
        const float nm1 = fmaxf(mrow[1], vmax1);
        const float corr0 = __expf(mrow[0] - nm0);
        const float corr1 = __expf(mrow[1] - nm1);

        float ts0 = 0.f, ts1 = 0.f;
#pragma unroll
        for (int ni = 0; ni < 4; ni++) {
            const int cj = wn * 32 + ni * 8 + 2 * t4;
            float p00 = __expf(cS[ni][0] - nm0);
            float p01 = __expf(cS[ni][1] - nm0);
            float p10 = __expf(cS[ni][2] - nm1);
            float p11 = __expf(cS[ni][3] - nm1);
            *(uint32_t*)&Ph[li0 * HST + cj] = pack_bf2(p00, p01);
            *(uint32_t*)&Ph[li1 * HST + cj] = pack_bf2(p10, p11);
            ts0 += p00 + p01;
            ts1 += p10 + p11;
        }
        ts0 += __shfl_xor_sync(0xffffffffu, ts0, 1);
        ts0 += __shfl_xor_sync(0xffffffffu, ts0, 2);
        ts1 += __shfl_xor_sync(0xffffffffu, ts1, 1);
        ts1 += __shfl_xor_sync(0xffffffffu, ts1, 2);
        if (t4 == 0) {
            Rsum[wn * 64 + li0] = ts0;
            Rsum[wn * 64 + li1] = ts1;
        }
        __syncthreads();
        ts0 += Rsum[(wn ^ 1) * 64 + li0];
        ts1 += Rsum[(wn ^ 1) * 64 + li1];

        lrow[0] = lrow[0] * corr0 + ts0;
        lrow[1] = lrow[1] * corr1 + ts1;
        mrow[0] = nm0;
        mrow[1] = nm1;
#pragma unroll
        for (int ni = 0; ni < 4; ni++) {
            O[ni][0] *= corr0;
            O[ni][1] *= corr0;
            O[ni][2] *= corr1;
            O[ni][3] *= corr1;
        }

#pragma unroll
        for (int kk = 0; kk < 4; kk++) {
            const int kb = kk * 16;
            uint32_t ap[4];
            ldsm_x4(ap, aP + kk * 32);
#pragma unroll
            for (int ni = 0; ni < 4; ni++) {
                const int nbase = wn * 32 + ni * 8;
                uint32_t bf[2];
                ldsm_x2t(bf, bVb[buf] + (kb * HST + nbase) * 2);
                mma_bf16(O[ni], ap, bf);
            }
        }
    }

    const float hscale = hm[h];
    const float inv0 = hscale / lrow[0];
    const float inv1 = hscale / lrow[1];
#pragma unroll
    for (int ni = 0; ni < 4; ni++) {
        const int col = h * HD + wn * 32 + ni * 8 + 2 * t4;
        const size_t row0g = (size_t)(b * SEQ + l0 + li0) * HID + col;
        const size_t row1g = (size_t)(b * SEQ + l0 + li1) * HID + col;
        *(uint32_t*)&ctx[row0g] = pack_hf2(O[ni][0] * inv0, O[ni][1] * inv0);
        *(uint32_t*)&ctx[row1g] = pack_hf2(O[ni][2] * inv1, O[ni][3] * inv1);
    }
}

// ---------------- launch ----------------
extern "C" void kernel_launch(void* const* d_in, const int* in_sizes, int n_in,
                              void* d_out, int out_size)
{
    const float* hs   = (const float*)d_in[0];
    const float* mask = (const float*)d_in[1];
    const float* hm   = (const float*)d_in[2];
    const float* Wq   = (const float*)d_in[3];
    const float* bq   = (const float*)d_in[4];
    const float* Wk   = (const float*)d_in[5];
    const float* bk   = (const float*)d_in[6];
    const float* Wv   = (const float*)d_in[7];
    const float* bv   = (const float*)d_in[8];
    const float* dist = (const float*)d_in[9];
    const float* Wo   = (const float*)d_in[10];
    const float* bo   = (const float*)d_in[11];
    const float* ln1g = (const float*)d_in[12];
    const float* ln1b = (const float*)d_in[13];
    const float* Wi   = (const float*)d_in[14];
    const float* bi   = (const float*)d_in[15];
    const float* Wo2  = (const float*)d_in[16];
    const float* bo2  = (const float*)d_in[17];
    const float* ln2g = (const float*)d_in[18];
    const float* ln2b = (const float*)d_in[19];
    float* out = (float*)d_out;

    __nv_bfloat16 *qh, *kh, *vh, *disth;
    __half *hs_h, *wq_h, *wk_h, *wv_h, *wo_h, *wi_h, *wo2_h;
    __half *ctx_h, *attnout_h, *inter_h;
    float *tmp, *attnout;
    cudaGetSymbolAddress((void**)&qh,        g_qh);
    cudaGetSymbolAddress((void**)&kh,        g_kh);
    cudaGetSymbolAddress((void**)&vh,        g_vh);
    cudaGetSymbolAddress((void**)&disth,     g_disth);
    cudaGetSymbolAddress((void**)&hs_h,      g_hs_h);
    cudaGetSymbolAddress((void**)&wq_h,      g_wq_h);
    cudaGetSymbolAddress((void**)&wk_h,      g_wk_h);
    cudaGetSymbolAddress((void**)&wv_h,      g_wv_h);
    cudaGetSymbolAddress((void**)&wo_h,      g_wo_h);
    cudaGetSymbolAddress((void**)&wi_h,      g_wi_h);
    cudaGetSymbolAddress((void**)&wo2_h,     g_wo2_h);
    cudaGetSymbolAddress((void**)&ctx_h,     g_ctx_h);
    cudaGetSymbolAddress((void**)&attnout_h, g_attnout_h);
    cudaGetSymbolAddress((void**)&inter_h,   g_inter_h);
    cudaGetSymbolAddress((void**)&tmp,       g_tmp);
    cudaGetSymbolAddress((void**)&attnout,   g_attnout);

    cudaFuncSetAttribute(attn_tc, cudaFuncAttributeMaxDynamicSharedMemorySize,
                         ATTN_SMEM_BYTES);
    cudaFuncSetAttribute((const void*)gemm_hf<0,0>,
                         cudaFuncAttributeMaxDynamicSharedMemorySize, GEMM_HF_SMEM);
    cudaFuncSetAttribute((const void*)gemm_hf<1,2>,
                         cudaFuncAttributeMaxDynamicSharedMemorySize, GEMM_HF_SMEM);
    cudaFuncSetAttribute((const void*)qkv_hf,
                         cudaFuncAttributeMaxDynamicSharedMemorySize, GEMM_HF_SMEM);

    dim3 blk(256);

    fused_cvt_k<<<(CVT_TOTAL + 255) / 256, blk>>>(
        Wq, Wk, Wv, Wo, Wi, Wo2, hs, dist,
        wq_h, wk_h, wv_h, wo_h, wi_h, wo2_h, hs_h, disth);

    dim3 g_qkv(HID / 128, NTOK / 128, 3);
    dim3 g_1024(HID / 128, NTOK / 128);
    dim3 g_ff1(FFDIM / 128, NTOK / 128);

    qkv_hf<<<g_qkv, blk, GEMM_HF_SMEM>>>(hs_h, wq_h, wk_h, wv_h, bq, bk, bv,
                                         qh, kh, vh);

    attn_tc<<<dim3(SEQ / 64, BATCH * NHEAD), blk, ATTN_SMEM_BYTES>>>(
        qh, kh, vh, disth, mask, hm, ctx_h);

    gemm_hf<0,0><<<g_1024, blk, GEMM_HF_SMEM>>>(ctx_h, wo_h, bo, tmp,
                                                NTOK, HID, HID);
    ln_residual<<<NTOK, blk>>>(tmp, hs, ln1g, ln1b, attnout, attnout_h);

    gemm_hf<1,2><<<g_ff1, blk, GEMM_HF_SMEM>>>(attnout_h, wi_h, bi, inter_h,
                                               NTOK, FFDIM, HID);
    gemm_hf<0,0><<<g_1024, blk, GEMM_HF_SMEM>>>(inter_h, wo2_h, bo2, tmp,
                                                NTOK, HID, FFDIM);
    ln_residual<<<NTOK, blk>>>(tmp, attnout, ln2g, ln2b, out, nullptr);
}